// round 8
// baseline (speedup 1.0000x reference)
#include <cuda_runtime.h>
#include <math.h>

// Problem constants
#define BB   2
#define TT   2048
#define CC   2048
#define NH_  16
#define HS_  128
#define NLQ_ 512
#define NLKV_ 512
#define DHR_ 64

// ---------------- scratch buffers (static device allocations) ----------------
__device__ __align__(16) float d_cq  [(size_t)BB*TT*NLQ_];          //  8 MB
__device__ __align__(16) float d_ckv [(size_t)BB*TT*NLKV_];         //  8 MB
__device__ __align__(16) float d_keff[(size_t)NH_*NLQ_*NLKV_];      // 16 MB
__device__ __align__(16) float d_vtmp[(size_t)NLKV_*CC];            //  4 MB
__device__ __align__(16) float d_qlat[(size_t)BB*NH_*TT*NLKV_];     // 128 MB
__device__ __align__(16) float d_qr  [(size_t)BB*TT*NH_*DHR_];      // 16 MB
__device__ __align__(16) float d_kr  [(size_t)BB*TT*DHR_];          //  1 MB
__device__ __align__(16) float d_ctx [(size_t)BB*NH_*TT*NLKV_];     // 128 MB

// ---------------- generic strided SGEMM ----------------
// C[z][m][n] = sum_k A[m*sAm + k*sAk] * B[n*sBn + k*sBk]
// z = b*H + h ; per-operand batch offsets via (sXb, sXh).
__global__ __launch_bounds__(256) void sgemm_g(
    const float* __restrict__ A, const float* __restrict__ B, float* __restrict__ C,
    int M, int N, int K,
    long long sAm, long long sAk, long long sAb, long long sAh,
    long long sBn, long long sBk, long long sBb, long long sBh,
    long long sCm, long long sCb, long long sCh, int H)
{
    __shared__ float As[16][68];
    __shared__ float Bs[16][68];

    int z = blockIdx.z;
    int bb = z / H, hh = z - bb * H;
    A += (size_t)bb * sAb + (size_t)hh * sAh;
    B += (size_t)bb * sBb + (size_t)hh * sBh;
    C += (size_t)bb * sCb + (size_t)hh * sCh;

    int m0 = blockIdx.y * 64, n0 = blockIdx.x * 64;
    int tid = threadIdx.x;
    int tx = tid & 15, ty = tid >> 4;

    float acc[4][4];
#pragma unroll
    for (int i = 0; i < 4; i++)
#pragma unroll
        for (int j = 0; j < 4; j++) acc[i][j] = 0.f;

    for (int k0 = 0; k0 < K; k0 += 16) {
#pragma unroll
        for (int u = 0; u < 4; u++) {
            int idx = tid * 4 + u;          // 0..1023
            int m = idx >> 4, kk = idx & 15;
            int gm = m0 + m, gk = k0 + kk;
            As[kk][m] = (gm < M && gk < K) ? A[(size_t)gm * sAm + (size_t)gk * sAk] : 0.f;
            int gn = n0 + m;
            Bs[kk][m] = (gn < N && gk < K) ? B[(size_t)gn * sBn + (size_t)gk * sBk] : 0.f;
        }
        __syncthreads();
#pragma unroll
        for (int kk = 0; kk < 16; kk++) {
            float4 av = *(const float4*)&As[kk][ty << 2];
            float4 bv = *(const float4*)&Bs[kk][tx << 2];
            float a[4] = {av.x, av.y, av.z, av.w};
            float b[4] = {bv.x, bv.y, bv.z, bv.w};
#pragma unroll
            for (int i = 0; i < 4; i++)
#pragma unroll
                for (int j = 0; j < 4; j++)
                    acc[i][j] = fmaf(a[i], b[j], acc[i][j]);
        }
        __syncthreads();
    }
#pragma unroll
    for (int i = 0; i < 4; i++) {
        int gm = m0 + (ty << 2) + i;
        if (gm >= M) continue;
#pragma unroll
        for (int j = 0; j < 4; j++) {
            int gn = n0 + (tx << 2) + j;
            if (gn < N) C[(size_t)gm * sCm + gn] = acc[i][j];
        }
    }
}

// ---------------- RoPE kernels (in-place) ----------------
__global__ void rope_qr_kernel(float* __restrict__ qr,
                               const float* __restrict__ cs, const float* __restrict__ sn)
{
    int idx = blockIdx.x * blockDim.x + threadIdx.x;     // over B*T*NH*32 pairs
    if (idx >= BB * TT * NH_ * 32) return;
    int i  = idx & 31;
    int h  = (idx >> 5) & 15;
    int bt = idx >> 9;
    int t  = bt & (TT - 1);
    float c = cs[t * 32 + i], s = sn[t * 32 + i];
    size_t base = (size_t)bt * (NH_ * DHR_) + h * DHR_ + 2 * i;
    float re = qr[base], im = qr[base + 1];
    qr[base]     = re * c - im * s;
    qr[base + 1] = re * s + im * c;
}

__global__ void rope_kr_kernel(float* __restrict__ kr,
                               const float* __restrict__ cs, const float* __restrict__ sn)
{
    int idx = blockIdx.x * blockDim.x + threadIdx.x;     // over B*T*32 pairs
    if (idx >= BB * TT * 32) return;
    int i  = idx & 31;
    int bt = idx >> 5;
    int t  = bt & (TT - 1);
    float c = cs[t * 32 + i], s = sn[t * 32 + i];
    size_t base = (size_t)bt * DHR_ + 2 * i;
    float re = kr[base], im = kr[base + 1];
    kr[base]     = re * c - im * s;
    kr[base + 1] = re * s + im * c;
}

// ---------------- fused flash-attention core ----------------
// Q[b,h,t,0:576] = [qlat | qr] (pre-scaled), K[b,s,0:576] = [ckv | kr], V = ckv.
// 64-query tiles, online softmax, ctx[b,h,t,0:512] output.
#define FPITCH 68
#define FSM_FLOATS (576*FPITCH + 64*FPITCH + 64*FPITCH + 64*17 + 4*64)

__global__ __launch_bounds__(256, 1) void flash_kernel(
    const float* __restrict__ qlat, const float* __restrict__ qr,
    const float* __restrict__ ckv,  const float* __restrict__ kr,
    float* __restrict__ ctx)
{
    extern __shared__ float sm[];
    float* Qs   = sm;                      // [576][68]  transposed: Qs[d][i]
    float* KVs  = Qs  + 576 * FPITCH;      // [64][68]
    float* Ps   = KVs + 64 * FPITCH;       // [64][68]
    float* Red  = Ps  + 64 * FPITCH;       // [64][17]
    float* msm  = Red + 64 * 17;
    float* lsm  = msm + 64;
    float* fsm  = lsm + 64;
    float* mnsm = fsm + 64;

    int qt = blockIdx.x, h = blockIdx.y, b = blockIdx.z;
    int t0 = qt * 64;
    int tid = threadIdx.x;
    int tx = tid & 15, ty = tid >> 4;
    const float scale = rsqrtf((float)(HS_ + DHR_));

    const float* qlatp = qlat + ((size_t)(b * NH_ + h) * TT + t0) * NLKV_;
    const float* qrp   = qr   + ((size_t)b * TT + t0) * (NH_ * DHR_) + h * DHR_;
    const float* ckvb  = ckv  + (size_t)b * TT * NLKV_;
    const float* krb   = kr   + (size_t)b * TT * DHR_;

    // load resident Q tile (transposed + scaled)
    for (int idx = tid; idx < 64 * 512; idx += 256) {
        int i = idx >> 9, d = idx & 511;
        Qs[d * FPITCH + i] = qlatp[(size_t)i * NLKV_ + d] * scale;
    }
    for (int idx = tid; idx < 64 * 64; idx += 256) {
        int i = idx >> 6, d = idx & 63;
        Qs[(512 + d) * FPITCH + i] = qrp[(size_t)i * (NH_ * DHR_) + d] * scale;
    }
    if (tid < 64) { msm[tid] = -1e30f; lsm[tid] = 0.f; }
    __syncthreads();

    float acc[4][8][4];
#pragma unroll
    for (int i = 0; i < 4; i++)
#pragma unroll
        for (int g = 0; g < 8; g++)
#pragma unroll
            for (int v = 0; v < 4; v++) acc[i][g][v] = 0.f;

    for (int kt = 0; kt <= qt; kt++) {
        int s0 = kt * 64;
        float S[4][4];
#pragma unroll
        for (int i = 0; i < 4; i++)
#pragma unroll
            for (int j = 0; j < 4; j++) S[i][j] = 0.f;

        // ---- scores: 9 d-chunks of 64 ----
        for (int dc = 0; dc < 9; dc++) {
            __syncthreads();
            {   // load K chunk transposed: KVs[d][j]
                int j = tid >> 2;
                int dbase = (tid & 3) * 16;
                const float* src = (dc < 8)
                    ? (ckvb + (size_t)(s0 + j) * NLKV_ + dc * 64 + dbase)
                    : (krb  + (size_t)(s0 + j) * DHR_ + dbase);
#pragma unroll
                for (int u = 0; u < 16; u += 4) {
                    float4 v = *(const float4*)(src + u);
                    KVs[(dbase + u + 0) * FPITCH + j] = v.x;
                    KVs[(dbase + u + 1) * FPITCH + j] = v.y;
                    KVs[(dbase + u + 2) * FPITCH + j] = v.z;
                    KVs[(dbase + u + 3) * FPITCH + j] = v.w;
                }
            }
            __syncthreads();
            const float* Qc = Qs + dc * 64 * FPITCH;
#pragma unroll 8
            for (int d = 0; d < 64; d++) {
                float4 qv = *(const float4*)(Qc  + d * FPITCH + (ty << 2));
                float4 kv = *(const float4*)(KVs + d * FPITCH + (tx << 2));
                float qa[4] = {qv.x, qv.y, qv.z, qv.w};
                float ka[4] = {kv.x, kv.y, kv.z, kv.w};
#pragma unroll
                for (int ii = 0; ii < 4; ii++)
#pragma unroll
                    for (int jj = 0; jj < 4; jj++)
                        S[ii][jj] = fmaf(qa[ii], ka[jj], S[ii][jj]);
            }
        }

        // causal mask on diagonal tile
        if (kt == qt) {
#pragma unroll
            for (int ii = 0; ii < 4; ii++)
#pragma unroll
                for (int jj = 0; jj < 4; jj++)
                    if ((tx << 2) + jj > (ty << 2) + ii) S[ii][jj] = -1e30f;
        }

        // ---- online softmax ----
#pragma unroll
        for (int ii = 0; ii < 4; ii++) {
            float mx = fmaxf(fmaxf(S[ii][0], S[ii][1]), fmaxf(S[ii][2], S[ii][3]));
            Red[((ty << 2) + ii) * 17 + tx] = mx;
        }
        __syncthreads();
        if (tid < 64) {
            float mx = -1e30f;
#pragma unroll
            for (int u = 0; u < 16; u++) mx = fmaxf(mx, Red[tid * 17 + u]);
            float mo = msm[tid];
            float mn = fmaxf(mo, mx);
            msm[tid]  = mn;
            mnsm[tid] = mn;
            fsm[tid]  = __expf(mo - mn);
        }
        __syncthreads();
#pragma unroll
        for (int ii = 0; ii < 4; ii++) {
            int i = (ty << 2) + ii;
            float mn = mnsm[i];
            float f  = fsm[i];
            float4 p;
            p.x = __expf(S[ii][0] - mn);
            p.y = __expf(S[ii][1] - mn);
            p.z = __expf(S[ii][2] - mn);
            p.w = __expf(S[ii][3] - mn);
            *(float4*)(Ps + i * FPITCH + (tx << 2)) = p;
            Red[i * 17 + tx] = p.x + p.y + p.z + p.w;
#pragma unroll
            for (int g = 0; g < 8; g++)
#pragma unroll
                for (int vv = 0; vv < 4; vv++) acc[ii][g][vv] *= f;
        }
        __syncthreads();
        if (tid < 64) {
            float sum = 0.f;
#pragma unroll
            for (int u = 0; u < 16; u++) sum += Red[tid * 17 + u];
            lsm[tid] = lsm[tid] * fsm[tid] + sum;
        }

        // ---- PV: 8 v-chunks of 64 ----
#pragma unroll
        for (int g = 0; g < 8; g++) {
            __syncthreads();
            {   // load V chunk (natural layout): KVs[j][v]
                int j = tid >> 2;
                int vbase = (tid & 3) * 16;
                const float* src = ckvb + (size_t)(s0 + j) * NLKV_ + g * 64 + vbase;
                float* dst = KVs + j * FPITCH + vbase;
#pragma unroll
                for (int u = 0; u < 16; u += 4)
                    *(float4*)(dst + u) = *(const float4*)(src + u);
            }
            __syncthreads();
#pragma unroll 4
            for (int j = 0; j < 64; j++) {
                float pr[4];
#pragma unroll
                for (int ii = 0; ii < 4; ii++) pr[ii] = Ps[((ty << 2) + ii) * FPITCH + j];
                float4 v = *(const float4*)(KVs + j * FPITCH + (tx << 2));
                float va[4] = {v.x, v.y, v.z, v.w};
#pragma unroll
                for (int ii = 0; ii < 4; ii++)
#pragma unroll
                    for (int vv = 0; vv < 4; vv++)
                        acc[ii][g][vv] = fmaf(pr[ii], va[vv], acc[ii][g][vv]);
            }
        }
    }

    // ---- write ctx ----
#pragma unroll
    for (int ii = 0; ii < 4; ii++) {
        int i = (ty << 2) + ii;
        float inv = 1.0f / lsm[i];
        float* orow = ctx + ((size_t)(b * NH_ + h) * TT + t0 + i) * NLKV_;
#pragma unroll
        for (int g = 0; g < 8; g++) {
            float4 o;
            o.x = acc[ii][g][0] * inv;
            o.y = acc[ii][g][1] * inv;
            o.z = acc[ii][g][2] * inv;
            o.w = acc[ii][g][3] * inv;
            *(float4*)(orow + g * 64 + (tx << 2)) = o;
        }
    }
}

// ---------------- launch ----------------
extern "C" void kernel_launch(void* const* d_in, const int* in_sizes, int n_in,
                              void* d_out, int out_size)
{
    (void)in_sizes; (void)n_in; (void)out_size;
    const float* x    = (const float*)d_in[0];
    const float* cs   = (const float*)d_in[1];
    const float* sn   = (const float*)d_in[2];
    const float* W_dq = (const float*)d_in[3];
    const float* W_uq = (const float*)d_in[4];
    const float* W_dkv= (const float*)d_in[5];
    const float* W_uk = (const float*)d_in[6];
    const float* W_uv = (const float*)d_in[7];
    const float* W_qr = (const float*)d_in[8];
    const float* W_kr = (const float*)d_in[9];
    const float* W_o  = (const float*)d_in[10];
    float* y = (float*)d_out;

    float *cq, *ckv, *keff, *vtmp, *qlat, *qr, *kr, *ctx;
    cudaGetSymbolAddress((void**)&cq,   d_cq);
    cudaGetSymbolAddress((void**)&ckv,  d_ckv);
    cudaGetSymbolAddress((void**)&keff, d_keff);
    cudaGetSymbolAddress((void**)&vtmp, d_vtmp);
    cudaGetSymbolAddress((void**)&qlat, d_qlat);
    cudaGetSymbolAddress((void**)&qr,   d_qr);
    cudaGetSymbolAddress((void**)&kr,   d_kr);
    cudaGetSymbolAddress((void**)&ctx,  d_ctx);

    const int MT = BB * TT;   // 4096

    // 1) c_q = x @ W_dq^T          (4096 x 512, K=2048)
    sgemm_g<<<dim3(NLQ_/64, MT/64, 1), 256>>>(x, W_dq, cq,
        MT, NLQ_, CC,  CC,1, 0,0,  CC,1, 0,0,  NLQ_, 0,0, 1);

    // 2) c_kv = x @ W_dkv^T        (4096 x 512, K=2048)
    sgemm_g<<<dim3(NLKV_/64, MT/64, 1), 256>>>(x, W_dkv, ckv,
        MT, NLKV_, CC,  CC,1, 0,0,  CC,1, 0,0,  NLKV_, 0,0, 1);

    // 3) k_eff[h,q,k] = sum_s Wuq[q*2048+h*128+s] * Wuk[h*65536+s*512+k]  (16 x 512x512, K=128)
    sgemm_g<<<dim3(NLKV_/64, NLQ_/64, NH_), 256>>>(W_uq, W_uk, keff,
        NLQ_, NLKV_, HS_,
        CC,1, 0,(long long)HS_,
        1,(long long)NLKV_, 0,(long long)HS_*NLKV_,
        NLKV_, 0,(long long)NLQ_*NLKV_, NH_);

    // 4) v_tmp[k,d] = sum_c W_uv[c,k] * W_o[d,c]   (512 x 2048, K=2048)
    sgemm_g<<<dim3(CC/64, NLKV_/64, 1), 256>>>(W_uv, W_o, vtmp,
        NLKV_, CC, CC,
        1,(long long)NLKV_, 0,0,
        CC,1, 0,0,
        CC, 0,0, 1);

    // 5) qr_lin = c_q @ W_qr^T     (4096 x 1024, K=512)
    sgemm_g<<<dim3((NH_*DHR_)/64, MT/64, 1), 256>>>(cq, W_qr, qr,
        MT, NH_*DHR_, NLQ_,  NLQ_,1, 0,0,  NLQ_,1, 0,0,  NH_*DHR_, 0,0, 1);

    // 6) kr_lin = x @ W_kr^T       (4096 x 64, K=2048)
    sgemm_g<<<dim3(1, MT/64, 1), 256>>>(x, W_kr, kr,
        MT, DHR_, CC,  CC,1, 0,0,  CC,1, 0,0,  DHR_, 0,0, 1);

    // 7) RoPE (in place)
    rope_qr_kernel<<<(BB*TT*NH_*32 + 255)/256, 256>>>(qr, cs, sn);
    rope_kr_kernel<<<(BB*TT*32 + 255)/256, 256>>>(kr, cs, sn);

    // 8) q_lat[b,h,t,k] = sum_q c_q[b,t,q] * k_eff[h,q,k]   (32 x 2048x512, K=512)
    sgemm_g<<<dim3(NLKV_/64, TT/64, BB*NH_), 256>>>(cq, keff, qlat,
        TT, NLKV_, NLQ_,
        NLQ_,1, (long long)TT*NLQ_, 0,
        1,(long long)NLKV_, 0,(long long)NLQ_*NLKV_,
        NLKV_, (long long)NH_*TT*NLKV_, (long long)TT*NLKV_, NH_);

    // 9) flash attention core -> ctx
    static const size_t smem_bytes = (size_t)FSM_FLOATS * sizeof(float);
    cudaFuncSetAttribute(flash_kernel, cudaFuncAttributeMaxDynamicSharedMemorySize,
                         (int)smem_bytes);
    flash_kernel<<<dim3(TT/64, NH_, BB), 256, smem_bytes>>>(qlat, qr, ckv, kr, ctx);

    // 10) y[b,t,h*128+d] = sum_k ctx[b,h,t,k] * v_tmp[k, h*128+d]  (32 x 2048x128, K=512)
    sgemm_g<<<dim3(HS_/64, TT/64, BB*NH_), 256>>>(ctx, vtmp, y,
        TT, HS_, NLKV_,
        NLKV_,1, (long long)NH_*TT*NLKV_, (long long)TT*NLKV_,
        1,(long long)CC, 0,(long long)HS_,
        CC, (long long)TT*CC, (long long)HS_, NH_);
}

// round 9
// speedup vs baseline: 2.1135x; 2.1135x over previous
#include <cuda_runtime.h>
#include <math.h>

// Problem constants
#define BB   2
#define TT   2048
#define CC   2048
#define NH_  16
#define HS_  128
#define NLQ_ 512
#define NLKV_ 512
#define DHR_ 64

// ---------------- scratch buffers ----------------
__device__ __align__(16) float d_cq  [(size_t)BB*TT*NLQ_];
__device__ __align__(16) float d_ckv [(size_t)BB*TT*NLKV_];
__device__ __align__(16) float d_keff[(size_t)NH_*NLQ_*NLKV_];
__device__ __align__(16) float d_vtmp[(size_t)NLKV_*CC];
__device__ __align__(16) float d_qlat[(size_t)BB*NH_*TT*NLKV_];
__device__ __align__(16) float d_qr  [(size_t)BB*TT*NH_*DHR_];
__device__ __align__(16) float d_kr  [(size_t)BB*TT*DHR_];
__device__ __align__(16) float d_ctx [(size_t)BB*NH_*TT*NLKV_];

// ---------------- tf32 helpers ----------------
__device__ __forceinline__ float tf(float x) {
    unsigned r; asm("cvt.rna.tf32.f32 %0, %1;" : "=r"(r) : "f"(x));
    return __uint_as_float(r);
}
__device__ __forceinline__ void mma8(float d[4], const unsigned a[4], const unsigned b[2]) {
    asm volatile(
        "mma.sync.aligned.m16n8k8.row.col.f32.tf32.tf32.f32 "
        "{%0,%1,%2,%3}, {%4,%5,%6,%7}, {%8,%9}, {%0,%1,%2,%3};\n"
        : "+f"(d[0]), "+f"(d[1]), "+f"(d[2]), "+f"(d[3])
        : "r"(a[0]), "r"(a[1]), "r"(a[2]), "r"(a[3]), "r"(b[0]), "r"(b[1]));
}

// ---------------- generic strided fp32 SGEMM (value path, accuracy-critical) ----------------
__global__ __launch_bounds__(256) void sgemm_g(
    const float* __restrict__ A, const float* __restrict__ B, float* __restrict__ C,
    int M, int N, int K,
    long long sAm, long long sAk, long long sAb, long long sAh,
    long long sBn, long long sBk, long long sBb, long long sBh,
    long long sCm, long long sCb, long long sCh, int H)
{
    __shared__ float As[16][68];
    __shared__ float Bs[16][68];

    int z = blockIdx.z;
    int bb = z / H, hh = z - bb * H;
    A += (size_t)bb * sAb + (size_t)hh * sAh;
    B += (size_t)bb * sBb + (size_t)hh * sBh;
    C += (size_t)bb * sCb + (size_t)hh * sCh;

    int m0 = blockIdx.y * 64, n0 = blockIdx.x * 64;
    int tid = threadIdx.x;
    int tx = tid & 15, ty = tid >> 4;

    float acc[4][4];
#pragma unroll
    for (int i = 0; i < 4; i++)
#pragma unroll
        for (int j = 0; j < 4; j++) acc[i][j] = 0.f;

    for (int k0 = 0; k0 < K; k0 += 16) {
#pragma unroll
        for (int u = 0; u < 4; u++) {
            int idx = tid * 4 + u;
            int m = idx >> 4, kk = idx & 15;
            int gm = m0 + m, gk = k0 + kk;
            As[kk][m] = (gm < M && gk < K) ? A[(size_t)gm * sAm + (size_t)gk * sAk] : 0.f;
            int gn = n0 + m;
            Bs[kk][m] = (gn < N && gk < K) ? B[(size_t)gn * sBn + (size_t)gk * sBk] : 0.f;
        }
        __syncthreads();
#pragma unroll
        for (int kk = 0; kk < 16; kk++) {
            float4 av = *(const float4*)&As[kk][ty << 2];
            float4 bv = *(const float4*)&Bs[kk][tx << 2];
            float a[4] = {av.x, av.y, av.z, av.w};
            float b[4] = {bv.x, bv.y, bv.z, bv.w};
#pragma unroll
            for (int i = 0; i < 4; i++)
#pragma unroll
                for (int j = 0; j < 4; j++)
                    acc[i][j] = fmaf(a[i], b[j], acc[i][j]);
        }
        __syncthreads();
    }
#pragma unroll
    for (int i = 0; i < 4; i++) {
        int gm = m0 + (ty << 2) + i;
        if (gm >= M) continue;
#pragma unroll
        for (int j = 0; j < 4; j++) {
            int gn = n0 + (tx << 2) + j;
            if (gn < N) C[(size_t)gm * sCm + gn] = acc[i][j];
        }
    }
}

// ---------------- generic strided tf32 tensor GEMM ----------------
// 128x128 block tile, 256 threads, warp grid 2(m) x 4(n), warp tile 64x32.
// REQUIRES: M % 128 == 0, N % 128 == 0, K % 16 == 0.
__global__ __launch_bounds__(256) void tgemm(
    const float* __restrict__ A, const float* __restrict__ B, float* __restrict__ C,
    int M, int N, int K,
    long long sAm, long long sAk, long long sAb, long long sAh,
    long long sBn, long long sBk, long long sBb, long long sBh,
    long long sCm, long long sCb, long long sCh, int H)
{
    __shared__ float As[16][136];   // [k][m]
    __shared__ float Bs[16][136];   // [k][n]

    int z = blockIdx.z;
    int bb = z / H, hh = z - bb * H;
    A += (size_t)bb * sAb + (size_t)hh * sAh;
    B += (size_t)bb * sBb + (size_t)hh * sBh;
    C += (size_t)bb * sCb + (size_t)hh * sCh;

    int m0 = blockIdx.y * 128, n0 = blockIdx.x * 128;
    int tid = threadIdx.x, lane = tid & 31, w = tid >> 5;
    int g = lane >> 2, tg = lane & 3;
    int wr = w & 1, wc = w >> 1;

    float acc[4][4][4];
#pragma unroll
    for (int i = 0; i < 4; i++)
#pragma unroll
        for (int j = 0; j < 4; j++)
#pragma unroll
            for (int c = 0; c < 4; c++) acc[i][j][c] = 0.f;

    for (int k0 = 0; k0 < K; k0 += 16) {
        if (sAk == 1) {
            int m = tid >> 1, kk = (tid & 1) * 8;
            const float* p = A + (size_t)(m0 + m) * sAm + k0 + kk;
            float4 v0 = *(const float4*)p;
            float4 v1 = *(const float4*)(p + 4);
            As[kk + 0][m] = tf(v0.x); As[kk + 1][m] = tf(v0.y);
            As[kk + 2][m] = tf(v0.z); As[kk + 3][m] = tf(v0.w);
            As[kk + 4][m] = tf(v1.x); As[kk + 5][m] = tf(v1.y);
            As[kk + 6][m] = tf(v1.z); As[kk + 7][m] = tf(v1.w);
        } else {
#pragma unroll
            for (int u = 0; u < 8; u++) {
                int idx = tid + u * 256;
                int kk = idx >> 7, m = idx & 127;
                As[kk][m] = tf(A[(size_t)(m0 + m) * sAm + (size_t)(k0 + kk) * sAk]);
            }
        }
        if (sBk == 1) {
            int n = tid >> 1, kk = (tid & 1) * 8;
            const float* p = B + (size_t)(n0 + n) * sBn + k0 + kk;
            float4 v0 = *(const float4*)p;
            float4 v1 = *(const float4*)(p + 4);
            Bs[kk + 0][n] = tf(v0.x); Bs[kk + 1][n] = tf(v0.y);
            Bs[kk + 2][n] = tf(v0.z); Bs[kk + 3][n] = tf(v0.w);
            Bs[kk + 4][n] = tf(v1.x); Bs[kk + 5][n] = tf(v1.y);
            Bs[kk + 6][n] = tf(v1.z); Bs[kk + 7][n] = tf(v1.w);
        } else {
#pragma unroll
            for (int u = 0; u < 8; u++) {
                int idx = tid + u * 256;
                int kk = idx >> 7, n = idx & 127;
                Bs[kk][n] = tf(B[(size_t)(n0 + n) * sBn + (size_t)(k0 + kk) * sBk]);
            }
        }
        __syncthreads();
#pragma unroll
        for (int kk2 = 0; kk2 < 2; kk2++) {
            int kb = kk2 * 8 + tg;
            unsigned a[4][4], bq[4][2];
#pragma unroll
            for (int ma = 0; ma < 4; ma++) {
                const float* p = &As[kb][wr * 64 + ma * 16 + g];
                a[ma][0] = __float_as_uint(p[0]);
                a[ma][1] = __float_as_uint(p[8]);
                a[ma][2] = __float_as_uint(p[4 * 136]);
                a[ma][3] = __float_as_uint(p[4 * 136 + 8]);
            }
#pragma unroll
            for (int na = 0; na < 4; na++) {
                const float* p = &Bs[kb][wc * 32 + na * 8 + g];
                bq[na][0] = __float_as_uint(p[0]);
                bq[na][1] = __float_as_uint(p[4 * 136]);
            }
#pragma unroll
            for (int ma = 0; ma < 4; ma++)
#pragma unroll
                for (int na = 0; na < 4; na++)
                    mma8(acc[ma][na], a[ma], bq[na]);
        }
        __syncthreads();
    }
#pragma unroll
    for (int ma = 0; ma < 4; ma++)
#pragma unroll
        for (int hf = 0; hf < 2; hf++) {
            int gm = m0 + wr * 64 + ma * 16 + hf * 8 + g;
#pragma unroll
            for (int na = 0; na < 4; na++) {
                int gn = n0 + wc * 32 + na * 8 + 2 * tg;
                float2 o;
                o.x = acc[ma][na][hf * 2];
                o.y = acc[ma][na][hf * 2 + 1];
                *(float2*)&C[(size_t)gm * sCm + gn] = o;
            }
        }
}

// ---------------- RoPE kernels (in-place) ----------------
__global__ void rope_qr_kernel(float* __restrict__ qr,
                               const float* __restrict__ cs, const float* __restrict__ sn)
{
    int idx = blockIdx.x * blockDim.x + threadIdx.x;
    if (idx >= BB * TT * NH_ * 32) return;
    int i  = idx & 31;
    int h  = (idx >> 5) & 15;
    int bt = idx >> 9;
    int t  = bt & (TT - 1);
    float c = cs[t * 32 + i], s = sn[t * 32 + i];
    size_t base = (size_t)bt * (NH_ * DHR_) + h * DHR_ + 2 * i;
    float re = qr[base], im = qr[base + 1];
    qr[base]     = re * c - im * s;
    qr[base + 1] = re * s + im * c;
}

__global__ void rope_kr_kernel(float* __restrict__ kr,
                               const float* __restrict__ cs, const float* __restrict__ sn)
{
    int idx = blockIdx.x * blockDim.x + threadIdx.x;
    if (idx >= BB * TT * 32) return;
    int i  = idx & 31;
    int bt = idx >> 5;
    int t  = bt & (TT - 1);
    float c = cs[t * 32 + i], s = sn[t * 32 + i];
    size_t base = (size_t)bt * DHR_ + 2 * i;
    float re = kr[base], im = kr[base + 1];
    kr[base]     = re * c - im * s;
    kr[base + 1] = re * s + im * c;
}

// ---------------- tf32 tensor-core flash attention ----------------
// Q resident (64 x 576, tf32, pre-scaled). 64-key tiles. Warp grid 2(m) x 4(n).
#define QP 580   // Qs pitch  (4 mod 32)
#define PP 68    // Ps pitch  (4 mod 32)
#define KP 72    // K chunk pitch (8 mod 32)
#define VP 520   // V chunk pitch (8 mod 32)
#define FTC_FLOATS (64*QP + 64*PP + 16*VP + 64*8 + 4*64)

__global__ __launch_bounds__(256, 1) void flash_tc(
    const float* __restrict__ qlat, const float* __restrict__ qr,
    const float* __restrict__ ckv,  const float* __restrict__ kr,
    float* __restrict__ ctx)
{
    extern __shared__ float smx[];
    float* Qs  = smx;                 // [64][QP]
    float* Ps  = Qs + 64 * QP;        // [64][PP]
    float* KVs = Ps + 64 * PP;        // union: K chunk [64][KP] / V chunk [16][VP]
    float* Red = KVs + 16 * VP;       // [64][8]: 0-3 max partials, 4-7 sum partials
    float* msm = Red + 64 * 8;
    float* lsm = msm + 64;
    float* fsm = lsm + 64;
    float* mns = fsm + 64;

    int qt = blockIdx.x, h = blockIdx.y, b = blockIdx.z;
    int t0 = qt * 64;
    int tid = threadIdx.x, lane = tid & 31, w = tid >> 5;
    int g = lane >> 2, tg = lane & 3;
    int wr = w & 1, wc = w >> 1;
    const float scale = rsqrtf((float)(HS_ + DHR_));

    const float* qlatp = qlat + ((size_t)(b * NH_ + h) * TT + t0) * NLKV_;
    const float* qrp   = qr   + ((size_t)b * TT + t0) * (NH_ * DHR_) + h * DHR_;
    const float* ckvb  = ckv  + (size_t)b * TT * NLKV_;
    const float* krb   = kr   + (size_t)b * TT * DHR_;

    // resident Q tile: [q][d], tf32, pre-scaled
#pragma unroll
    for (int it = 0; it < 32; it++) {
        int i4 = tid + it * 256;                  // 0..8191
        int i = i4 >> 7, d = (i4 & 127) * 4;
        float4 v = *(const float4*)(qlatp + (size_t)i * NLKV_ + d);
        float4 o;
        o.x = tf(v.x * scale); o.y = tf(v.y * scale);
        o.z = tf(v.z * scale); o.w = tf(v.w * scale);
        *(float4*)(Qs + i * QP + d) = o;
    }
#pragma unroll
    for (int it = 0; it < 4; it++) {
        int i4 = tid + it * 256;                  // 0..1023
        int i = i4 >> 4, d = (i4 & 15) * 4;
        float4 v = *(const float4*)(qrp + (size_t)i * (NH_ * DHR_) + d);
        float4 o;
        o.x = tf(v.x * scale); o.y = tf(v.y * scale);
        o.z = tf(v.z * scale); o.w = tf(v.w * scale);
        *(float4*)(Qs + i * QP + 512 + d) = o;
    }
    if (tid < 64) { msm[tid] = -1e30f; lsm[tid] = 0.f; }

    float O[2][16][4];
#pragma unroll
    for (int ma = 0; ma < 2; ma++)
#pragma unroll
        for (int na = 0; na < 16; na++)
#pragma unroll
            for (int c = 0; c < 4; c++) O[ma][na][c] = 0.f;

    for (int kt = 0; kt <= qt; kt++) {
        int s0 = kt * 64;
        float S[2][2][4];
#pragma unroll
        for (int ma = 0; ma < 2; ma++)
#pragma unroll
            for (int na = 0; na < 2; na++)
#pragma unroll
                for (int c = 0; c < 4; c++) S[ma][na][c] = 0.f;

        // ---- scores: 9 d-chunks of 64 ----
        for (int dc = 0; dc < 9; dc++) {
            __syncthreads();
            {   // K chunk transposed: KVs[d][key]
                int j = tid >> 2;
                int db = (tid & 3) * 16;
                const float* src = (dc < 8)
                    ? (ckvb + (size_t)(s0 + j) * NLKV_ + dc * 64 + db)
                    : (krb  + (size_t)(s0 + j) * DHR_ + db);
#pragma unroll
                for (int u = 0; u < 16; u += 4) {
                    float4 v = *(const float4*)(src + u);
                    KVs[(db + u + 0) * KP + j] = tf(v.x);
                    KVs[(db + u + 1) * KP + j] = tf(v.y);
                    KVs[(db + u + 2) * KP + j] = tf(v.z);
                    KVs[(db + u + 3) * KP + j] = tf(v.w);
                }
            }
            __syncthreads();
            const float* Qc = Qs + dc * 64;
#pragma unroll
            for (int kk = 0; kk < 8; kk++) {
                unsigned a[2][4], bq[2][2];
#pragma unroll
                for (int ma = 0; ma < 2; ma++) {
                    const float* p = Qc + (wr * 32 + ma * 16 + g) * QP + kk * 8 + tg;
                    a[ma][0] = __float_as_uint(p[0]);
                    a[ma][1] = __float_as_uint(p[8 * QP]);
                    a[ma][2] = __float_as_uint(p[4]);
                    a[ma][3] = __float_as_uint(p[8 * QP + 4]);
                }
#pragma unroll
                for (int na = 0; na < 2; na++) {
                    const float* p = KVs + (kk * 8 + tg) * KP + wc * 16 + na * 8 + g;
                    bq[na][0] = __float_as_uint(p[0]);
                    bq[na][1] = __float_as_uint(p[4 * KP]);
                }
#pragma unroll
                for (int ma = 0; ma < 2; ma++)
#pragma unroll
                    for (int na = 0; na < 2; na++)
                        mma8(S[ma][na], a[ma], bq[na]);
            }
        }

        // causal mask on diagonal tile
        if (kt == qt) {
#pragma unroll
            for (int ma = 0; ma < 2; ma++)
#pragma unroll
                for (int na = 0; na < 2; na++)
#pragma unroll
                    for (int ci = 0; ci < 4; ci++) {
                        int row = wr * 32 + ma * 16 + (ci >> 1) * 8 + g;
                        int col = wc * 16 + na * 8 + 2 * tg + (ci & 1);
                        if (col > row) S[ma][na][ci] = -1e30f;
                    }
        }

        // ---- row max ----
#pragma unroll
        for (int ma = 0; ma < 2; ma++)
#pragma unroll
            for (int hf = 0; hf < 2; hf++) {
                float v = fmaxf(fmaxf(S[ma][0][hf * 2], S[ma][0][hf * 2 + 1]),
                                fmaxf(S[ma][1][hf * 2], S[ma][1][hf * 2 + 1]));
                v = fmaxf(v, __shfl_xor_sync(0xffffffffu, v, 1));
                v = fmaxf(v, __shfl_xor_sync(0xffffffffu, v, 2));
                if (tg == 0)
                    Red[(wr * 32 + ma * 16 + hf * 8 + g) * 8 + wc] = v;
            }
        __syncthreads();
        if (tid < 64) {
            float mx = fmaxf(fmaxf(Red[tid * 8 + 0], Red[tid * 8 + 1]),
                             fmaxf(Red[tid * 8 + 2], Red[tid * 8 + 3]));
            float mo = msm[tid];
            float mn = fmaxf(mo, mx);
            msm[tid] = mn; mns[tid] = mn;
            fsm[tid] = __expf(mo - mn);
        }
        __syncthreads();

        // ---- exp, write P (tf32), partial sums, rescale O ----
#pragma unroll
        for (int ma = 0; ma < 2; ma++)
#pragma unroll
            for (int hf = 0; hf < 2; hf++) {
                int row = wr * 32 + ma * 16 + hf * 8 + g;
                float mn = mns[row];
                float s = 0.f;
#pragma unroll
                for (int na = 0; na < 2; na++) {
                    float p0 = __expf(S[ma][na][hf * 2 + 0] - mn);
                    float p1 = __expf(S[ma][na][hf * 2 + 1] - mn);
                    s += p0 + p1;
                    float2 pv; pv.x = tf(p0); pv.y = tf(p1);
                    *(float2*)(Ps + row * PP + wc * 16 + na * 8 + 2 * tg) = pv;
                }
                s += __shfl_xor_sync(0xffffffffu, s, 1);
                s += __shfl_xor_sync(0xffffffffu, s, 2);
                if (tg == 0) Red[row * 8 + 4 + wc] = s;
            }
#pragma unroll
        for (int ma = 0; ma < 2; ma++) {
            float f0 = fsm[wr * 32 + ma * 16 + g];
            float f1 = fsm[wr * 32 + ma * 16 + 8 + g];
#pragma unroll
            for (int na = 0; na < 16; na++) {
                O[ma][na][0] *= f0; O[ma][na][1] *= f0;
                O[ma][na][2] *= f1; O[ma][na][3] *= f1;
            }
        }
        __syncthreads();
        if (tid < 64)
            lsm[tid] = lsm[tid] * fsm[tid] +
                       Red[tid * 8 + 4] + Red[tid * 8 + 5] +
                       Red[tid * 8 + 6] + Red[tid * 8 + 7];

        // ---- PV: 4 s-chunks of 16 ----
        for (int cc = 0; cc < 4; cc++) {
            __syncthreads();
#pragma unroll
            for (int it = 0; it < 8; it++) {      // V chunk [16][512] -> tf32
                int i4 = tid + it * 256;
                int s = i4 >> 7, v4 = (i4 & 127) * 4;
                float4 v = *(const float4*)(ckvb + (size_t)(s0 + cc * 16 + s) * NLKV_ + v4);
                float4 o;
                o.x = tf(v.x); o.y = tf(v.y); o.z = tf(v.z); o.w = tf(v.w);
                *(float4*)(KVs + s * VP + v4) = o;
            }
            __syncthreads();
#pragma unroll
            for (int kk = 0; kk < 2; kk++) {
                unsigned a[2][4];
                int sc = cc * 16 + kk * 8 + tg;
#pragma unroll
                for (int ma = 0; ma < 2; ma++) {
                    const float* p = Ps + (wr * 32 + ma * 16 + g) * PP + sc;
                    a[ma][0] = __float_as_uint(p[0]);
                    a[ma][1] = __float_as_uint(p[8 * PP]);
                    a[ma][2] = __float_as_uint(p[4]);
                    a[ma][3] = __float_as_uint(p[8 * PP + 4]);
                }
#pragma unroll
                for (int na = 0; na < 16; na++) {
                    const float* p = KVs + (kk * 8 + tg) * VP + wc * 128 + na * 8 + g;
                    unsigned bq[2];
                    bq[0] = __float_as_uint(p[0]);
                    bq[1] = __float_as_uint(p[4 * VP]);
                    mma8(O[0][na], a[0], bq);
                    mma8(O[1][na], a[1], bq);
                }
            }
        }
    }

    __syncthreads();
    // ---- epilogue: normalize and write ctx ----
#pragma unroll
    for (int ma = 0; ma < 2; ma++)
#pragma unroll
        for (int hf = 0; hf < 2; hf++) {
            int row = wr * 32 + ma * 16 + hf * 8 + g;
            float inv = 1.0f / lsm[row];
            float* orow = ctx + ((size_t)(b * NH_ + h) * TT + t0 + row) * NLKV_;
#pragma unroll
            for (int na = 0; na < 16; na++) {
                float2 o;
                o.x = O[ma][na][hf * 2]     * inv;
                o.y = O[ma][na][hf * 2 + 1] * inv;
                *(float2*)(orow + wc * 128 + na * 8 + 2 * tg) = o;
            }
        }
}

// ---------------- launch ----------------
extern "C" void kernel_launch(void* const* d_in, const int* in_sizes, int n_in,
                              void* d_out, int out_size)
{
    (void)in_sizes; (void)n_in; (void)out_size;
    const float* x    = (const float*)d_in[0];
    const float* cs   = (const float*)d_in[1];
    const float* sn   = (const float*)d_in[2];
    const float* W_dq = (const float*)d_in[3];
    const float* W_uq = (const float*)d_in[4];
    const float* W_dkv= (const float*)d_in[5];
    const float* W_uk = (const float*)d_in[6];
    const float* W_uv = (const float*)d_in[7];
    const float* W_qr = (const float*)d_in[8];
    const float* W_kr = (const float*)d_in[9];
    const float* W_o  = (const float*)d_in[10];
    float* y = (float*)d_out;

    float *cq, *ckv, *keff, *vtmp, *qlat, *qr, *kr, *ctx;
    cudaGetSymbolAddress((void**)&cq,   d_cq);
    cudaGetSymbolAddress((void**)&ckv,  d_ckv);
    cudaGetSymbolAddress((void**)&keff, d_keff);
    cudaGetSymbolAddress((void**)&vtmp, d_vtmp);
    cudaGetSymbolAddress((void**)&qlat, d_qlat);
    cudaGetSymbolAddress((void**)&qr,   d_qr);
    cudaGetSymbolAddress((void**)&kr,   d_kr);
    cudaGetSymbolAddress((void**)&ctx,  d_ctx);

    const int MT = BB * TT;   // 4096

    // 1) c_q = x @ W_dq^T   (tf32; score path)
    tgemm<<<dim3(NLQ_/128, MT/128, 1), 256>>>(x, W_dq, cq,
        MT, NLQ_, CC,  CC,1, 0,0,  CC,1, 0,0,  NLQ_, 0,0, 1);

    // 2) c_kv = x @ W_dkv^T   (fp32; value path)
    sgemm_g<<<dim3(NLKV_/64, MT/64, 1), 256>>>(x, W_dkv, ckv,
        MT, NLKV_, CC,  CC,1, 0,0,  CC,1, 0,0,  NLKV_, 0,0, 1);

    // 3) k_eff  (tf32; score path)
    tgemm<<<dim3(NLKV_/128, NLQ_/128, NH_), 256>>>(W_uq, W_uk, keff,
        NLQ_, NLKV_, HS_,
        CC,1, 0,(long long)HS_,
        1,(long long)NLKV_, 0,(long long)HS_*NLKV_,
        NLKV_, 0,(long long)NLQ_*NLKV_, NH_);

    // 4) v_tmp = W_uv^T @ W_o^T   (fp32; value path)
    sgemm_g<<<dim3(CC/64, NLKV_/64, 1), 256>>>(W_uv, W_o, vtmp,
        NLKV_, CC, CC,
        1,(long long)NLKV_, 0,0,
        CC,1, 0,0,
        CC, 0,0, 1);

    // 5) qr_lin = c_q @ W_qr^T   (tf32; score path)
    tgemm<<<dim3((NH_*DHR_)/128, MT/128, 1), 256>>>(cq, W_qr, qr,
        MT, NH_*DHR_, NLQ_,  NLQ_,1, 0,0,  NLQ_,1, 0,0,  NH_*DHR_, 0,0, 1);

    // 6) kr_lin = x @ W_kr^T   (fp32, small)
    sgemm_g<<<dim3(1, MT/64, 1), 256>>>(x, W_kr, kr,
        MT, DHR_, CC,  CC,1, 0,0,  CC,1, 0,0,  DHR_, 0,0, 1);

    // 7) RoPE (in place)
    rope_qr_kernel<<<(BB*TT*NH_*32 + 255)/256, 256>>>(qr, cs, sn);
    rope_kr_kernel<<<(BB*TT*32 + 255)/256, 256>>>(kr, cs, sn);

    // 8) q_lat = c_q @ k_eff   (tf32; score path, large)
    tgemm<<<dim3(NLKV_/128, TT/128, BB*NH_), 256>>>(cq, keff, qlat,
        TT, NLKV_, NLQ_,
        NLQ_,1, (long long)TT*NLQ_, 0,
        1,(long long)NLKV_, 0,(long long)NLQ_*NLKV_,
        NLKV_, (long long)NH_*TT*NLKV_, (long long)TT*NLKV_, NH_);

    // 9) flash attention core (tf32 tensor cores) -> ctx
    static const size_t smem_bytes = (size_t)FTC_FLOATS * sizeof(float);
    cudaFuncSetAttribute(flash_tc, cudaFuncAttributeMaxDynamicSharedMemorySize,
                         (int)smem_bytes);
    flash_tc<<<dim3(TT/64, NH_, BB), 256, smem_bytes>>>(qlat, qr, ckv, kr, ctx);

    // 10) y = ctx @ v_eff   (fp32; value path)
    sgemm_g<<<dim3(HS_/64, TT/64, BB*NH_), 256>>>(ctx, vtmp, y,
        TT, HS_, NLKV_,
        NLKV_,1, (long long)NH_*TT*NLKV_, (long long)TT*NLKV_,
        1,(long long)CC, 0,(long long)HS_,
        CC, (long long)TT*CC, (long long)HS_, NH_);
}

// round 12
// speedup vs baseline: 2.3783x; 1.1253x over previous
#include <cuda_runtime.h>
#include <math.h>

// Problem constants
#define BB   2
#define TT   2048
#define CC   2048
#define NH_  16
#define HS_  128
#define NLQ_ 512
#define NLKV_ 512
#define DHR_ 64

// ---------------- scratch buffers ----------------
__device__ __align__(16) float d_cq  [(size_t)BB*TT*NLQ_];
__device__ __align__(16) float d_ckv [(size_t)BB*TT*NLKV_];
__device__ __align__(16) float d_keff[(size_t)NH_*NLQ_*NLKV_];
__device__ __align__(16) float d_vtmp[(size_t)NLKV_*CC];
__device__ __align__(16) float d_qlat[(size_t)BB*NH_*TT*NLKV_];
__device__ __align__(16) float d_qr  [(size_t)BB*TT*NH_*DHR_];
__device__ __align__(16) float d_kr  [(size_t)BB*TT*DHR_];
__device__ __align__(16) float d_ctx [(size_t)BB*NH_*TT*NLKV_];

// ---------------- tf32 helpers ----------------
__device__ __forceinline__ float tf(float x) {
    unsigned r; asm("cvt.rna.tf32.f32 %0, %1;" : "=r"(r) : "f"(x));
    return __uint_as_float(r);
}
__device__ __forceinline__ void mma8(float d[4], const unsigned a[4], const unsigned b[2]) {
    asm volatile(
        "mma.sync.aligned.m16n8k8.row.col.f32.tf32.tf32.f32 "
        "{%0,%1,%2,%3}, {%4,%5,%6,%7}, {%8,%9}, {%0,%1,%2,%3};\n"
        : "+f"(d[0]), "+f"(d[1]), "+f"(d[2]), "+f"(d[3])
        : "r"(a[0]), "r"(a[1]), "r"(a[2]), "r"(a[3]), "r"(b[0]), "r"(b[1]));
}

// ---------------- generic strided fp32 SGEMM (small leftovers only) ----------------
__global__ __launch_bounds__(256) void sgemm_g(
    const float* __restrict__ A, const float* __restrict__ B, float* __restrict__ C,
    int M, int N, int K,
    long long sAm, long long sAk, long long sAb, long long sAh,
    long long sBn, long long sBk, long long sBb, long long sBh,
    long long sCm, long long sCb, long long sCh, int H)
{
    __shared__ float As[16][68];
    __shared__ float Bs[16][68];

    int z = blockIdx.z;
    int bb = z / H, hh = z - bb * H;
    A += (size_t)bb * sAb + (size_t)hh * sAh;
    B += (size_t)bb * sBb + (size_t)hh * sBh;
    C += (size_t)bb * sCb + (size_t)hh * sCh;

    int m0 = blockIdx.y * 64, n0 = blockIdx.x * 64;
    int tid = threadIdx.x;
    int tx = tid & 15, ty = tid >> 4;

    float acc[4][4];
#pragma unroll
    for (int i = 0; i < 4; i++)
#pragma unroll
        for (int j = 0; j < 4; j++) acc[i][j] = 0.f;

    for (int k0 = 0; k0 < K; k0 += 16) {
#pragma unroll
        for (int u = 0; u < 4; u++) {
            int idx = tid * 4 + u;
            int m = idx >> 4, kk = idx & 15;
            int gm = m0 + m, gk = k0 + kk;
            As[kk][m] = (gm < M && gk < K) ? A[(size_t)gm * sAm + (size_t)gk * sAk] : 0.f;
            int gn = n0 + m;
            Bs[kk][m] = (gn < N && gk < K) ? B[(size_t)gn * sBn + (size_t)gk * sBk] : 0.f;
        }
        __syncthreads();
#pragma unroll
        for (int kk = 0; kk < 16; kk++) {
            float4 av = *(const float4*)&As[kk][ty << 2];
            float4 bv = *(const float4*)&Bs[kk][tx << 2];
            float a[4] = {av.x, av.y, av.z, av.w};
            float b[4] = {bv.x, bv.y, bv.z, bv.w};
#pragma unroll
            for (int i = 0; i < 4; i++)
#pragma unroll
                for (int j = 0; j < 4; j++)
                    acc[i][j] = fmaf(a[i], b[j], acc[i][j]);
        }
        __syncthreads();
    }
#pragma unroll
    for (int i = 0; i < 4; i++) {
        int gm = m0 + (ty << 2) + i;
        if (gm >= M) continue;
#pragma unroll
        for (int j = 0; j < 4; j++) {
            int gn = n0 + (tx << 2) + j;
            if (gn < N) C[(size_t)gm * sCm + gn] = acc[i][j];
        }
    }
}

// ---------------- generic strided tf32 tensor GEMM ----------------
// 128x128 block tile, 256 threads, warp grid 2(m) x 4(n), warp tile 64x32.
// REQUIRES: M % 128 == 0, N % 128 == 0, K % 16 == 0.
__global__ __launch_bounds__(256) void tgemm(
    const float* __restrict__ A, const float* __restrict__ B, float* __restrict__ C,
    int M, int N, int K,
    long long sAm, long long sAk, long long sAb, long long sAh,
    long long sBn, long long sBk, long long sBb, long long sBh,
    long long sCm, long long sCb, long long sCh, int H)
{
    __shared__ float As[16][136];   // [k][m]
    __shared__ float Bs[16][136];   // [k][n]

    int z = blockIdx.z;
    int bb = z / H, hh = z - bb * H;
    A += (size_t)bb * sAb + (size_t)hh * sAh;
    B += (size_t)bb * sBb + (size_t)hh * sBh;
    C += (size_t)bb * sCb + (size_t)hh * sCh;

    int m0 = blockIdx.y * 128, n0 = blockIdx.x * 128;
    int tid = threadIdx.x, lane = tid & 31, w = tid >> 5;
    int g = lane >> 2, tg = lane & 3;
    int wr = w & 1, wc = w >> 1;

    float acc[4][4][4];
#pragma unroll
    for (int i = 0; i < 4; i++)
#pragma unroll
        for (int j = 0; j < 4; j++)
#pragma unroll
            for (int c = 0; c < 4; c++) acc[i][j][c] = 0.f;

    for (int k0 = 0; k0 < K; k0 += 16) {
        if (sAk == 1) {
            int m = tid >> 1, kk = (tid & 1) * 8;
            const float* p = A + (size_t)(m0 + m) * sAm + k0 + kk;
            float4 v0 = *(const float4*)p;
            float4 v1 = *(const float4*)(p + 4);
            As[kk + 0][m] = tf(v0.x); As[kk + 1][m] = tf(v0.y);
            As[kk + 2][m] = tf(v0.z); As[kk + 3][m] = tf(v0.w);
            As[kk + 4][m] = tf(v1.x); As[kk + 5][m] = tf(v1.y);
            As[kk + 6][m] = tf(v1.z); As[kk + 7][m] = tf(v1.w);
        } else {
#pragma unroll
            for (int u = 0; u < 8; u++) {
                int idx = tid + u * 256;
                int kk = idx >> 7, m = idx & 127;
                As[kk][m] = tf(A[(size_t)(m0 + m) * sAm + (size_t)(k0 + kk) * sAk]);
            }
        }
        if (sBk == 1) {
            int n = tid >> 1, kk = (tid & 1) * 8;
            const float* p = B + (size_t)(n0 + n) * sBn + k0 + kk;
            float4 v0 = *(const float4*)p;
            float4 v1 = *(const float4*)(p + 4);
            Bs[kk + 0][n] = tf(v0.x); Bs[kk + 1][n] = tf(v0.y);
            Bs[kk + 2][n] = tf(v0.z); Bs[kk + 3][n] = tf(v0.w);
            Bs[kk + 4][n] = tf(v1.x); Bs[kk + 5][n] = tf(v1.y);
            Bs[kk + 6][n] = tf(v1.z); Bs[kk + 7][n] = tf(v1.w);
        } else {
#pragma unroll
            for (int u = 0; u < 8; u++) {
                int idx = tid + u * 256;
                int kk = idx >> 7, n = idx & 127;
                Bs[kk][n] = tf(B[(size_t)(n0 + n) * sBn + (size_t)(k0 + kk) * sBk]);
            }
        }
        __syncthreads();
#pragma unroll
        for (int kk2 = 0; kk2 < 2; kk2++) {
            int kb = kk2 * 8 + tg;
            unsigned a[4][4], bq[4][2];
#pragma unroll
            for (int ma = 0; ma < 4; ma++) {
                const float* p = &As[kb][wr * 64 + ma * 16 + g];
                a[ma][0] = __float_as_uint(p[0]);
                a[ma][1] = __float_as_uint(p[8]);
                a[ma][2] = __float_as_uint(p[4 * 136]);
                a[ma][3] = __float_as_uint(p[4 * 136 + 8]);
            }
#pragma unroll
            for (int na = 0; na < 4; na++) {
                const float* p = &Bs[kb][wc * 32 + na * 8 + g];
                bq[na][0] = __float_as_uint(p[0]);
                bq[na][1] = __float_as_uint(p[4 * 136]);
            }
#pragma unroll
            for (int ma = 0; ma < 4; ma++)
#pragma unroll
                for (int na = 0; na < 4; na++)
                    mma8(acc[ma][na], a[ma], bq[na]);
        }
        __syncthreads();
    }
#pragma unroll
    for (int ma = 0; ma < 4; ma++)
#pragma unroll
        for (int hf = 0; hf < 2; hf++) {
            int gm = m0 + wr * 64 + ma * 16 + hf * 8 + g;
#pragma unroll
            for (int na = 0; na < 4; na++) {
                int gn = n0 + wc * 32 + na * 8 + 2 * tg;
                float2 o;
                o.x = acc[ma][na][hf * 2];
                o.y = acc[ma][na][hf * 2 + 1];
                *(float2*)&C[(size_t)gm * sCm + gn] = o;
            }
        }
}

// ---------------- RoPE kernels (in-place) ----------------
__global__ void rope_qr_kernel(float* __restrict__ qr,
                               const float* __restrict__ cs, const float* __restrict__ sn)
{
    int idx = blockIdx.x * blockDim.x + threadIdx.x;
    if (idx >= BB * TT * NH_ * 32) return;
    int i  = idx & 31;
    int h  = (idx >> 5) & 15;
    int bt = idx >> 9;
    int t  = bt & (TT - 1);
    float c = cs[t * 32 + i], s = sn[t * 32 + i];
    size_t base = (size_t)bt * (NH_ * DHR_) + h * DHR_ + 2 * i;
    float re = qr[base], im = qr[base + 1];
    qr[base]     = re * c - im * s;
    qr[base + 1] = re * s + im * c;
}

__global__ void rope_kr_kernel(float* __restrict__ kr,
                               const float* __restrict__ cs, const float* __restrict__ sn)
{
    int idx = blockIdx.x * blockDim.x + threadIdx.x;
    if (idx >= BB * TT * 32) return;
    int i  = idx & 31;
    int bt = idx >> 5;
    int t  = bt & (TT - 1);
    float c = cs[t * 32 + i], s = sn[t * 32 + i];
    size_t base = (size_t)bt * DHR_ + 2 * i;
    float re = kr[base], im = kr[base + 1];
    kr[base]     = re * c - im * s;
    kr[base + 1] = re * s + im * c;
}

// ---------------- tf32 tensor-core flash attention ----------------
// Q resident (64 x 576, tf32, pre-scaled). 64-key tiles. Warp grid 2(m) x 4(n).
#define QP 580   // Qs pitch  (4 mod 32)
#define PP 68    // Ps pitch  (4 mod 32)
#define KP 72    // K chunk pitch (8 mod 32)
#define VP 520   // V chunk pitch (8 mod 32)
#define FTC_FLOATS (64*QP + 64*PP + 16*VP + 64*8 + 4*64)

__global__ __launch_bounds__(256, 1) void flash_tc(
    const float* __restrict__ qlat, const float* __restrict__ qr,
    const float* __restrict__ ckv,  const float* __restrict__ kr,
    float* __restrict__ ctx)
{
    extern __shared__ float smx[];
    float* Qs  = smx;                 // [64][QP]
    float* Ps  = Qs + 64 * QP;        // [64][PP]
    float* KVs = Ps + 64 * PP;        // union: K chunk [64][KP] / V chunk [16][VP]
    float* Red = KVs + 16 * VP;       // [64][8]: 0-3 max partials, 4-7 sum partials
    float* msm = Red + 64 * 8;
    float* lsm = msm + 64;
    float* fsm = lsm + 64;
    float* mns = fsm + 64;

    int qt = blockIdx.x, h = blockIdx.y, b = blockIdx.z;
    int t0 = qt * 64;
    int tid = threadIdx.x, lane = tid & 31, w = tid >> 5;
    int g = lane >> 2, tg = lane & 3;
    int wr = w & 1, wc = w >> 1;
    const float scale = rsqrtf((float)(HS_ + DHR_));

    const float* qlatp = qlat + ((size_t)(b * NH_ + h) * TT + t0) * NLKV_;
    const float* qrp   = qr   + ((size_t)b * TT + t0) * (NH_ * DHR_) + h * DHR_;
    const float* ckvb  = ckv  + (size_t)b * TT * NLKV_;
    const float* krb   = kr   + (size_t)b * TT * DHR_;

    // resident Q tile: [q][d], tf32, pre-scaled
#pragma unroll
    for (int it = 0; it < 32; it++) {
        int i4 = tid + it * 256;
        int i = i4 >> 7, d = (i4 & 127) * 4;
        float4 v = *(const float4*)(qlatp + (size_t)i * NLKV_ + d);
        float4 o;
        o.x = tf(v.x * scale); o.y = tf(v.y * scale);
        o.z = tf(v.z * scale); o.w = tf(v.w * scale);
        *(float4*)(Qs + i * QP + d) = o;
    }
#pragma unroll
    for (int it = 0; it < 4; it++) {
        int i4 = tid + it * 256;
        int i = i4 >> 4, d = (i4 & 15) * 4;
        float4 v = *(const float4*)(qrp + (size_t)i * (NH_ * DHR_) + d);
        float4 o;
        o.x = tf(v.x * scale); o.y = tf(v.y * scale);
        o.z = tf(v.z * scale); o.w = tf(v.w * scale);
        *(float4*)(Qs + i * QP + 512 + d) = o;
    }
    if (tid < 64) { msm[tid] = -1e30f; lsm[tid] = 0.f; }

    float O[2][16][4];
#pragma unroll
    for (int ma = 0; ma < 2; ma++)
#pragma unroll
        for (int na = 0; na < 16; na++)
#pragma unroll
            for (int c = 0; c < 4; c++) O[ma][na][c] = 0.f;

    for (int kt = 0; kt <= qt; kt++) {
        int s0 = kt * 64;
        float S[2][2][4];
#pragma unroll
        for (int ma = 0; ma < 2; ma++)
#pragma unroll
            for (int na = 0; na < 2; na++)
#pragma unroll
                for (int c = 0; c < 4; c++) S[ma][na][c] = 0.f;

        // ---- scores: 9 d-chunks of 64 ----
        for (int dc = 0; dc < 9; dc++) {
            __syncthreads();
            {   // K chunk transposed: KVs[d][key]
                int j = tid >> 2;
                int db = (tid & 3) * 16;
                const float* src = (dc < 8)
                    ? (ckvb + (size_t)(s0 + j) * NLKV_ + dc * 64 + db)
                    : (krb  + (size_t)(s0 + j) * DHR_ + db);
#pragma unroll
                for (int u = 0; u < 16; u += 4) {
                    float4 v = *(const float4*)(src + u);
                    KVs[(db + u + 0) * KP + j] = tf(v.x);
                    KVs[(db + u + 1) * KP + j] = tf(v.y);
                    KVs[(db + u + 2) * KP + j] = tf(v.z);
                    KVs[(db + u + 3) * KP + j] = tf(v.w);
                }
            }
            __syncthreads();
            const float* Qc = Qs + dc * 64;
#pragma unroll
            for (int kk = 0; kk < 8; kk++) {
                unsigned a[2][4], bq[2][2];
#pragma unroll
                for (int ma = 0; ma < 2; ma++) {
                    const float* p = Qc + (wr * 32 + ma * 16 + g) * QP + kk * 8 + tg;
                    a[ma][0] = __float_as_uint(p[0]);
                    a[ma][1] = __float_as_uint(p[8 * QP]);
                    a[ma][2] = __float_as_uint(p[4]);
                    a[ma][3] = __float_as_uint(p[8 * QP + 4]);
                }
#pragma unroll
                for (int na = 0; na < 2; na++) {
                    const float* p = KVs + (kk * 8 + tg) * KP + wc * 16 + na * 8 + g;
                    bq[na][0] = __float_as_uint(p[0]);
                    bq[na][1] = __float_as_uint(p[4 * KP]);
                }
#pragma unroll
                for (int ma = 0; ma < 2; ma++)
#pragma unroll
                    for (int na = 0; na < 2; na++)
                        mma8(S[ma][na], a[ma], bq[na]);
            }
        }

        // causal mask on diagonal tile
        if (kt == qt) {
#pragma unroll
            for (int ma = 0; ma < 2; ma++)
#pragma unroll
                for (int na = 0; na < 2; na++)
#pragma unroll
                    for (int ci = 0; ci < 4; ci++) {
                        int row = wr * 32 + ma * 16 + (ci >> 1) * 8 + g;
                        int col = wc * 16 + na * 8 + 2 * tg + (ci & 1);
                        if (col > row) S[ma][na][ci] = -1e30f;
                    }
        }

        // ---- row max ----
#pragma unroll
        for (int ma = 0; ma < 2; ma++)
#pragma unroll
            for (int hf = 0; hf < 2; hf++) {
                float v = fmaxf(fmaxf(S[ma][0][hf * 2], S[ma][0][hf * 2 + 1]),
                                fmaxf(S[ma][1][hf * 2], S[ma][1][hf * 2 + 1]));
                v = fmaxf(v, __shfl_xor_sync(0xffffffffu, v, 1));
                v = fmaxf(v, __shfl_xor_sync(0xffffffffu, v, 2));
                if (tg == 0)
                    Red[(wr * 32 + ma * 16 + hf * 8 + g) * 8 + wc] = v;
            }
        __syncthreads();
        if (tid < 64) {
            float mx = fmaxf(fmaxf(Red[tid * 8 + 0], Red[tid * 8 + 1]),
                             fmaxf(Red[tid * 8 + 2], Red[tid * 8 + 3]));
            float mo = msm[tid];
            float mn = fmaxf(mo, mx);
            msm[tid] = mn; mns[tid] = mn;
            fsm[tid] = __expf(mo - mn);
        }
        __syncthreads();

        // ---- exp, write P (tf32), partial sums, rescale O ----
#pragma unroll
        for (int ma = 0; ma < 2; ma++)
#pragma unroll
            for (int hf = 0; hf < 2; hf++) {
                int row = wr * 32 + ma * 16 + hf * 8 + g;
                float mn = mns[row];
                float s = 0.f;
#pragma unroll
                for (int na = 0; na < 2; na++) {
                    float p0 = __expf(S[ma][na][hf * 2 + 0] - mn);
                    float p1 = __expf(S[ma][na][hf * 2 + 1] - mn);
                    s += p0 + p1;
                    float2 pv; pv.x = tf(p0); pv.y = tf(p1);
                    *(float2*)(Ps + row * PP + wc * 16 + na * 8 + 2 * tg) = pv;
                }
                s += __shfl_xor_sync(0xffffffffu, s, 1);
                s += __shfl_xor_sync(0xffffffffu, s, 2);
                if (tg == 0) Red[row * 8 + 4 + wc] = s;
            }
#pragma unroll
        for (int ma = 0; ma < 2; ma++) {
            float f0 = fsm[wr * 32 + ma * 16 + g];
            float f1 = fsm[wr * 32 + ma * 16 + 8 + g];
#pragma unroll
            for (int na = 0; na < 16; na++) {
                O[ma][na][0] *= f0; O[ma][na][1] *= f0;
                O[ma][na][2] *= f1; O[ma][na][3] *= f1;
            }
        }
        __syncthreads();
        if (tid < 64)
            lsm[tid] = lsm[tid] * fsm[tid] +
                       Red[tid * 8 + 4] + Red[tid * 8 + 5] +
                       Red[tid * 8 + 6] + Red[tid * 8 + 7];

        // ---- PV: 4 s-chunks of 16 ----
        for (int cc = 0; cc < 4; cc++) {
            __syncthreads();
#pragma unroll
            for (int it = 0; it < 8; it++) {      // V chunk [16][512] -> tf32
                int i4 = tid + it * 256;
                int s = i4 >> 7, v4 = (i4 & 127) * 4;
                float4 v = *(const float4*)(ckvb + (size_t)(s0 + cc * 16 + s) * NLKV_ + v4);
                float4 o;
                o.x = tf(v.x); o.y = tf(v.y); o.z = tf(v.z); o.w = tf(v.w);
                *(float4*)(KVs + s * VP + v4) = o;
            }
            __syncthreads();
#pragma unroll
            for (int kk = 0; kk < 2; kk++) {
                unsigned a[2][4];
                int sc = cc * 16 + kk * 8 + tg;
#pragma unroll
                for (int ma = 0; ma < 2; ma++) {
                    const float* p = Ps + (wr * 32 + ma * 16 + g) * PP + sc;
                    a[ma][0] = __float_as_uint(p[0]);
                    a[ma][1] = __float_as_uint(p[8 * PP]);
                    a[ma][2] = __float_as_uint(p[4]);
                    a[ma][3] = __float_as_uint(p[8 * PP + 4]);
                }
#pragma unroll
                for (int na = 0; na < 16; na++) {
                    const float* p = KVs + (kk * 8 + tg) * VP + wc * 128 + na * 8 + g;
                    unsigned bq[2];
                    bq[0] = __float_as_uint(p[0]);
                    bq[1] = __float_as_uint(p[4 * VP]);
                    mma8(O[0][na], a[0], bq);
                    mma8(O[1][na], a[1], bq);
                }
            }
        }
    }

    __syncthreads();
    // ---- epilogue: normalize and write ctx ----
#pragma unroll
    for (int ma = 0; ma < 2; ma++)
#pragma unroll
        for (int hf = 0; hf < 2; hf++) {
            int row = wr * 32 + ma * 16 + hf * 8 + g;
            float inv = 1.0f / lsm[row];
            float* orow = ctx + ((size_t)(b * NH_ + h) * TT + t0 + row) * NLKV_;
#pragma unroll
            for (int na = 0; na < 16; na++) {
                float2 o;
                o.x = O[ma][na][hf * 2]     * inv;
                o.y = O[ma][na][hf * 2 + 1] * inv;
                *(float2*)(orow + wc * 128 + na * 8 + 2 * tg) = o;
            }
        }
}

// ---------------- launch ----------------
extern "C" void kernel_launch(void* const* d_in, const int* in_sizes, int n_in,
                              void* d_out, int out_size)
{
    (void)in_sizes; (void)n_in; (void)out_size;
    const float* x    = (const float*)d_in[0];
    const float* cs   = (const float*)d_in[1];
    const float* sn   = (const float*)d_in[2];
    const float* W_dq = (const float*)d_in[3];
    const float* W_uq = (const float*)d_in[4];
    const float* W_dkv= (const float*)d_in[5];
    const float* W_uk = (const float*)d_in[6];
    const float* W_uv = (const float*)d_in[7];
    const float* W_qr = (const float*)d_in[8];
    const float* W_kr = (const float*)d_in[9];
    const float* W_o  = (const float*)d_in[10];
    float* y = (float*)d_out;

    float *cq, *ckv, *keff, *vtmp, *qlat, *qr, *kr, *ctx;
    cudaGetSymbolAddress((void**)&cq,   d_cq);
    cudaGetSymbolAddress((void**)&ckv,  d_ckv);
    cudaGetSymbolAddress((void**)&keff, d_keff);
    cudaGetSymbolAddress((void**)&vtmp, d_vtmp);
    cudaGetSymbolAddress((void**)&qlat, d_qlat);
    cudaGetSymbolAddress((void**)&qr,   d_qr);
    cudaGetSymbolAddress((void**)&kr,   d_kr);
    cudaGetSymbolAddress((void**)&ctx,  d_ctx);

    const int MT = BB * TT;   // 4096

    // 1) c_q = x @ W_dq^T   (tf32)
    tgemm<<<dim3(NLQ_/128, MT/128, 1), 256>>>(x, W_dq, cq,
        MT, NLQ_, CC,  CC,1, 0,0,  CC,1, 0,0,  NLQ_, 0,0, 1);

    // 2) c_kv = x @ W_dkv^T   (tf32)
    tgemm<<<dim3(NLKV_/128, MT/128, 1), 256>>>(x, W_dkv, ckv,
        MT, NLKV_, CC,  CC,1, 0,0,  CC,1, 0,0,  NLKV_, 0,0, 1);

    // 3) k_eff  (tf32)
    tgemm<<<dim3(NLKV_/128, NLQ_/128, NH_), 256>>>(W_uq, W_uk, keff,
        NLQ_, NLKV_, HS_,
        CC,1, 0,(long long)HS_,
        1,(long long)NLKV_, 0,(long long)HS_*NLKV_,
        NLKV_, 0,(long long)NLQ_*NLKV_, NH_);

    // 4) v_tmp = W_uv^T @ W_o^T   (tf32)
    tgemm<<<dim3(CC/128, NLKV_/128, 1), 256>>>(W_uv, W_o, vtmp,
        NLKV_, CC, CC,
        1,(long long)NLKV_, 0,0,
        CC,1, 0,0,
        CC, 0,0, 1);

    // 5) qr_lin = c_q @ W_qr^T   (tf32)
    tgemm<<<dim3((NH_*DHR_)/128, MT/128, 1), 256>>>(cq, W_qr, qr,
        MT, NH_*DHR_, NLQ_,  NLQ_,1, 0,0,  NLQ_,1, 0,0,  NH_*DHR_, 0,0, 1);

    // 6) kr_lin = x @ W_kr^T   (fp32, small: N=64)
    sgemm_g<<<dim3(1, MT/64, 1), 256>>>(x, W_kr, kr,
        MT, DHR_, CC,  CC,1, 0,0,  CC,1, 0,0,  DHR_, 0,0, 1);

    // 7) RoPE (in place)
    rope_qr_kernel<<<(BB*TT*NH_*32 + 255)/256, 256>>>(qr, cs, sn);
    rope_kr_kernel<<<(BB*TT*32 + 255)/256, 256>>>(kr, cs, sn);

    // 8) q_lat = c_q @ k_eff   (tf32, large)
    tgemm<<<dim3(NLKV_/128, TT/128, BB*NH_), 256>>>(cq, keff, qlat,
        TT, NLKV_, NLQ_,
        NLQ_,1, (long long)TT*NLQ_, 0,
        1,(long long)NLKV_, 0,(long long)NLQ_*NLKV_,
        NLKV_, (long long)NH_*TT*NLKV_, (long long)TT*NLKV_, NH_);

    // 9) flash attention core (tf32 tensor cores) -> ctx
    static const size_t smem_bytes = (size_t)FTC_FLOATS * sizeof(float);
    cudaFuncSetAttribute(flash_tc, cudaFuncAttributeMaxDynamicSharedMemorySize,
                         (int)smem_bytes);
    flash_tc<<<dim3(TT/64, NH_, BB), 256, smem_bytes>>>(qlat, qr, ckv, kr, ctx);

    // 10) y = ctx @ v_eff   (tf32; N=128 per head)
    tgemm<<<dim3(HS_/128, TT/128, BB*NH_), 256>>>(ctx, vtmp, y,
        TT, HS_, NLKV_,
        NLKV_,1, (long long)NH_*TT*NLKV_, (long long)TT*NLKV_,
        1,(long long)CC, 0,(long long)HS_,
        CC, (long long)TT*CC, (long long)HS_, NH_);
}

// round 13
// speedup vs baseline: 2.6417x; 1.1107x over previous
#include <cuda_runtime.h>
#include <math.h>

// Problem constants
#define BB   2
#define TT   2048
#define CC   2048
#define NH_  16
#define HS_  128
#define NLQ_ 512
#define NLKV_ 512
#define DHR_ 64

// ---------------- scratch buffers ----------------
__device__ __align__(16) float d_cq  [(size_t)BB*TT*NLQ_];
__device__ __align__(16) float d_ckv [(size_t)BB*TT*NLKV_];
__device__ __align__(16) float d_keff[(size_t)NH_*NLQ_*NLKV_];
__device__ __align__(16) float d_vtmp[(size_t)NLKV_*CC];
__device__ __align__(16) float d_qlat[(size_t)BB*NH_*TT*NLKV_];
__device__ __align__(16) float d_qr  [(size_t)BB*TT*NH_*DHR_];
__device__ __align__(16) float d_kr  [(size_t)BB*TT*DHR_];
__device__ __align__(16) float d_ctx [(size_t)BB*NH_*TT*NLKV_];

// ---------------- tf32 helpers ----------------
__device__ __forceinline__ float tf(float x) {
    unsigned r; asm("cvt.rna.tf32.f32 %0, %1;" : "=r"(r) : "f"(x));
    return __uint_as_float(r);
}
__device__ __forceinline__ void mma8(float d[4], const unsigned a[4], const unsigned b[2]) {
    asm volatile(
        "mma.sync.aligned.m16n8k8.row.col.f32.tf32.tf32.f32 "
        "{%0,%1,%2,%3}, {%4,%5,%6,%7}, {%8,%9}, {%0,%1,%2,%3};\n"
        : "+f"(d[0]), "+f"(d[1]), "+f"(d[2]), "+f"(d[3])
        : "r"(a[0]), "r"(a[1]), "r"(a[2]), "r"(a[3]), "r"(b[0]), "r"(b[1]));
}

// ---------------- generic strided fp32 SGEMM (small leftovers only) ----------------
__global__ __launch_bounds__(256) void sgemm_g(
    const float* __restrict__ A, const float* __restrict__ B, float* __restrict__ C,
    int M, int N, int K,
    long long sAm, long long sAk, long long sAb, long long sAh,
    long long sBn, long long sBk, long long sBb, long long sBh,
    long long sCm, long long sCb, long long sCh, int H)
{
    __shared__ float As[16][68];
    __shared__ float Bs[16][68];

    int z = blockIdx.z;
    int bb = z / H, hh = z - bb * H;
    A += (size_t)bb * sAb + (size_t)hh * sAh;
    B += (size_t)bb * sBb + (size_t)hh * sBh;
    C += (size_t)bb * sCb + (size_t)hh * sCh;

    int m0 = blockIdx.y * 64, n0 = blockIdx.x * 64;
    int tid = threadIdx.x;
    int tx = tid & 15, ty = tid >> 4;

    float acc[4][4];
#pragma unroll
    for (int i = 0; i < 4; i++)
#pragma unroll
        for (int j = 0; j < 4; j++) acc[i][j] = 0.f;

    for (int k0 = 0; k0 < K; k0 += 16) {
#pragma unroll
        for (int u = 0; u < 4; u++) {
            int idx = tid * 4 + u;
            int m = idx >> 4, kk = idx & 15;
            int gm = m0 + m, gk = k0 + kk;
            As[kk][m] = (gm < M && gk < K) ? A[(size_t)gm * sAm + (size_t)gk * sAk] : 0.f;
            int gn = n0 + m;
            Bs[kk][m] = (gn < N && gk < K) ? B[(size_t)gn * sBn + (size_t)gk * sBk] : 0.f;
        }
        __syncthreads();
#pragma unroll
        for (int kk = 0; kk < 16; kk++) {
            float4 av = *(const float4*)&As[kk][ty << 2];
            float4 bv = *(const float4*)&Bs[kk][tx << 2];
            float a[4] = {av.x, av.y, av.z, av.w};
            float b[4] = {bv.x, bv.y, bv.z, bv.w};
#pragma unroll
            for (int i = 0; i < 4; i++)
#pragma unroll
                for (int j = 0; j < 4; j++)
                    acc[i][j] = fmaf(a[i], b[j], acc[i][j]);
        }
        __syncthreads();
    }
#pragma unroll
    for (int i = 0; i < 4; i++) {
        int gm = m0 + (ty << 2) + i;
        if (gm >= M) continue;
#pragma unroll
        for (int j = 0; j < 4; j++) {
            int gn = n0 + (tx << 2) + j;
            if (gn < N) C[(size_t)gm * sCm + gn] = acc[i][j];
        }
    }
}

// ---------------- generic strided tf32 tensor GEMM (double-buffered, pipelined) ----------------
// 128x128 block tile, 256 threads, warp grid 2(m) x 4(n), warp tile 64x32.
// REQUIRES: M % 128 == 0, N % 128 == 0, K % 16 == 0.
__global__ __launch_bounds__(256) void tgemm(
    const float* __restrict__ A, const float* __restrict__ B, float* __restrict__ C,
    int M, int N, int K,
    long long sAm, long long sAk, long long sAb, long long sAh,
    long long sBn, long long sBk, long long sBb, long long sBh,
    long long sCm, long long sCb, long long sCh, int H)
{
    __shared__ float As[2][16][136];   // [buf][k][m]
    __shared__ float Bs[2][16][136];   // [buf][k][n]

    int z = blockIdx.z;
    int bb = z / H, hh = z - bb * H;
    A += (size_t)bb * sAb + (size_t)hh * sAh;
    B += (size_t)bb * sBb + (size_t)hh * sBh;
    C += (size_t)bb * sCb + (size_t)hh * sCh;

    int m0 = blockIdx.y * 128, n0 = blockIdx.x * 128;
    int tid = threadIdx.x, lane = tid & 31, w = tid >> 5;
    int g = lane >> 2, tg = lane & 3;
    int wr = w & 1, wc = w >> 1;

    float acc[4][4][4];
#pragma unroll
    for (int i = 0; i < 4; i++)
#pragma unroll
        for (int j = 0; j < 4; j++)
#pragma unroll
            for (int c = 0; c < 4; c++) acc[i][j][c] = 0.f;

    float ra[8], rb[8];

    auto fetchA = [&](int kof) {
        if (sAk == 1) {
            int m = tid >> 1, kk = (tid & 1) * 8;
            const float* p = A + (size_t)(m0 + m) * sAm + kof + kk;
            float4 v0 = *(const float4*)p;
            float4 v1 = *(const float4*)(p + 4);
            ra[0] = v0.x; ra[1] = v0.y; ra[2] = v0.z; ra[3] = v0.w;
            ra[4] = v1.x; ra[5] = v1.y; ra[6] = v1.z; ra[7] = v1.w;
        } else {
#pragma unroll
            for (int u = 0; u < 8; u++) {
                int idx = tid + u * 256;
                int kk = idx >> 7, m = idx & 127;
                ra[u] = A[(size_t)(m0 + m) * sAm + (size_t)(kof + kk) * sAk];
            }
        }
    };
    auto storeA = [&](int bf) {
        if (sAk == 1) {
            int m = tid >> 1, kk = (tid & 1) * 8;
#pragma unroll
            for (int u = 0; u < 8; u++) As[bf][kk + u][m] = tf(ra[u]);
        } else {
#pragma unroll
            for (int u = 0; u < 8; u++) {
                int idx = tid + u * 256;
                int kk = idx >> 7, m = idx & 127;
                As[bf][kk][m] = tf(ra[u]);
            }
        }
    };
    auto fetchB = [&](int kof) {
        if (sBk == 1) {
            int n = tid >> 1, kk = (tid & 1) * 8;
            const float* p = B + (size_t)(n0 + n) * sBn + kof + kk;
            float4 v0 = *(const float4*)p;
            float4 v1 = *(const float4*)(p + 4);
            rb[0] = v0.x; rb[1] = v0.y; rb[2] = v0.z; rb[3] = v0.w;
            rb[4] = v1.x; rb[5] = v1.y; rb[6] = v1.z; rb[7] = v1.w;
        } else {
#pragma unroll
            for (int u = 0; u < 8; u++) {
                int idx = tid + u * 256;
                int kk = idx >> 7, n = idx & 127;
                rb[u] = B[(size_t)(n0 + n) * sBn + (size_t)(kof + kk) * sBk];
            }
        }
    };
    auto storeB = [&](int bf) {
        if (sBk == 1) {
            int n = tid >> 1, kk = (tid & 1) * 8;
#pragma unroll
            for (int u = 0; u < 8; u++) Bs[bf][kk + u][n] = tf(rb[u]);
        } else {
#pragma unroll
            for (int u = 0; u < 8; u++) {
                int idx = tid + u * 256;
                int kk = idx >> 7, n = idx & 127;
                Bs[bf][kk][n] = tf(rb[u]);
            }
        }
    };

    const int KT = K >> 4;
    fetchA(0); fetchB(0);
    storeA(0); storeB(0);
    __syncthreads();

    for (int kt = 0; kt < KT; kt++) {
        int cur = kt & 1;
        if (kt + 1 < KT) { fetchA((kt + 1) << 4); fetchB((kt + 1) << 4); }
#pragma unroll
        for (int kk2 = 0; kk2 < 2; kk2++) {
            int kb = kk2 * 8 + tg;
            unsigned a[4][4], bq[4][2];
#pragma unroll
            for (int ma = 0; ma < 4; ma++) {
                const float* p = &As[cur][kb][wr * 64 + ma * 16 + g];
                a[ma][0] = __float_as_uint(p[0]);
                a[ma][1] = __float_as_uint(p[8]);
                a[ma][2] = __float_as_uint(p[4 * 136]);
                a[ma][3] = __float_as_uint(p[4 * 136 + 8]);
            }
#pragma unroll
            for (int na = 0; na < 4; na++) {
                const float* p = &Bs[cur][kb][wc * 32 + na * 8 + g];
                bq[na][0] = __float_as_uint(p[0]);
                bq[na][1] = __float_as_uint(p[4 * 136]);
            }
#pragma unroll
            for (int ma = 0; ma < 4; ma++)
#pragma unroll
                for (int na = 0; na < 4; na++)
                    mma8(acc[ma][na], a[ma], bq[na]);
        }
        if (kt + 1 < KT) { storeA(cur ^ 1); storeB(cur ^ 1); }
        __syncthreads();
    }
#pragma unroll
    for (int ma = 0; ma < 4; ma++)
#pragma unroll
        for (int hf = 0; hf < 2; hf++) {
            int gm = m0 + wr * 64 + ma * 16 + hf * 8 + g;
#pragma unroll
            for (int na = 0; na < 4; na++) {
                int gn = n0 + wc * 32 + na * 8 + 2 * tg;
                float2 o;
                o.x = acc[ma][na][hf * 2];
                o.y = acc[ma][na][hf * 2 + 1];
                *(float2*)&C[(size_t)gm * sCm + gn] = o;
            }
        }
}

// ---------------- RoPE kernels (in-place) ----------------
__global__ void rope_qr_kernel(float* __restrict__ qr,
                               const float* __restrict__ cs, const float* __restrict__ sn)
{
    int idx = blockIdx.x * blockDim.x + threadIdx.x;
    if (idx >= BB * TT * NH_ * 32) return;
    int i  = idx & 31;
    int h  = (idx >> 5) & 15;
    int bt = idx >> 9;
    int t  = bt & (TT - 1);
    float c = cs[t * 32 + i], s = sn[t * 32 + i];
    size_t base = (size_t)bt * (NH_ * DHR_) + h * DHR_ + 2 * i;
    float re = qr[base], im = qr[base + 1];
    qr[base]     = re * c - im * s;
    qr[base + 1] = re * s + im * c;
}

__global__ void rope_kr_kernel(float* __restrict__ kr,
                               const float* __restrict__ cs, const float* __restrict__ sn)
{
    int idx = blockIdx.x * blockDim.x + threadIdx.x;
    if (idx >= BB * TT * 32) return;
    int i  = idx & 31;
    int bt = idx >> 5;
    int t  = bt & (TT - 1);
    float c = cs[t * 32 + i], s = sn[t * 32 + i];
    size_t base = (size_t)bt * DHR_ + 2 * i;
    float re = kr[base], im = kr[base + 1];
    kr[base]     = re * c - im * s;
    kr[base + 1] = re * s + im * c;
}

// ---------------- tf32 tensor-core flash attention (double-buffered K/V) ----------------
// Q resident (64 x 576, tf32, pre-scaled). 64-key tiles. Warp grid 2(m) x 4(n).
#define QP 580            // Qs pitch  (4 mod 32)
#define PP 68             // Ps pitch  (4 mod 32)
#define KP 72             // K chunk pitch (8 mod 32)
#define VP 520            // V chunk pitch (8 mod 32)
#define KBUF (64 * KP)    // 4608 floats per K buffer
#define VBUF (8 * VP)     // 4160 floats per V buffer (8-row chunks)
#define KVSZ (2 * KBUF)   // 9216 floats (>= 2*VBUF)
#define FTC_FLOATS (64*QP + 64*PP + KVSZ + 64*8 + 4*64)

__global__ __launch_bounds__(256, 1) void flash_tc(
    const float* __restrict__ qlat, const float* __restrict__ qr,
    const float* __restrict__ ckv,  const float* __restrict__ kr,
    float* __restrict__ ctx)
{
    extern __shared__ float smx[];
    float* Qs  = smx;                 // [64][QP]
    float* Ps  = Qs + 64 * QP;        // [64][PP]
    float* KVs = Ps + 64 * PP;        // union: 2x K buf [64][KP] / 2x V buf [8][VP]
    float* Red = KVs + KVSZ;          // [64][8]: 0-3 max partials, 4-7 sum partials
    float* msm = Red + 64 * 8;
    float* lsm = msm + 64;
    float* fsm = lsm + 64;
    float* mns = fsm + 64;

    int qt = blockIdx.x, h = blockIdx.y, b = blockIdx.z;
    int t0 = qt * 64;
    int tid = threadIdx.x, lane = tid & 31, w = tid >> 5;
    int g = lane >> 2, tg = lane & 3;
    int wr = w & 1, wc = w >> 1;
    const float scale = rsqrtf((float)(HS_ + DHR_));

    const float* qlatp = qlat + ((size_t)(b * NH_ + h) * TT + t0) * NLKV_;
    const float* qrp   = qr   + ((size_t)b * TT + t0) * (NH_ * DHR_) + h * DHR_;
    const float* ckvb  = ckv  + (size_t)b * TT * NLKV_;
    const float* krb   = kr   + (size_t)b * TT * DHR_;

    // resident Q tile: [q][d], tf32, pre-scaled
#pragma unroll
    for (int it = 0; it < 32; it++) {
        int i4 = tid + it * 256;
        int i = i4 >> 7, d = (i4 & 127) * 4;
        float4 v = *(const float4*)(qlatp + (size_t)i * NLKV_ + d);
        float4 o;
        o.x = tf(v.x * scale); o.y = tf(v.y * scale);
        o.z = tf(v.z * scale); o.w = tf(v.w * scale);
        *(float4*)(Qs + i * QP + d) = o;
    }
#pragma unroll
    for (int it = 0; it < 4; it++) {
        int i4 = tid + it * 256;
        int i = i4 >> 4, d = (i4 & 15) * 4;
        float4 v = *(const float4*)(qrp + (size_t)i * (NH_ * DHR_) + d);
        float4 o;
        o.x = tf(v.x * scale); o.y = tf(v.y * scale);
        o.z = tf(v.z * scale); o.w = tf(v.w * scale);
        *(float4*)(Qs + i * QP + 512 + d) = o;
    }
    if (tid < 64) { msm[tid] = -1e30f; lsm[tid] = 0.f; }

    float O[2][16][4];
#pragma unroll
    for (int ma = 0; ma < 2; ma++)
#pragma unroll
        for (int na = 0; na < 16; na++)
#pragma unroll
            for (int c = 0; c < 4; c++) O[ma][na][c] = 0.f;

    for (int kt = 0; kt <= qt; kt++) {
        int s0 = kt * 64;

        // K chunk loader: chunk dc (0..8) transposed into kb: kb[d][key]
        auto loadK = [&](int dc, float* kb) {
            int j = tid >> 2;
            int db = (tid & 3) * 16;
            const float* src = (dc < 8)
                ? (ckvb + (size_t)(s0 + j) * NLKV_ + dc * 64 + db)
                : (krb  + (size_t)(s0 + j) * DHR_ + db);
#pragma unroll
            for (int u = 0; u < 16; u += 4) {
                float4 v = *(const float4*)(src + u);
                kb[(db + u + 0) * KP + j] = tf(v.x);
                kb[(db + u + 1) * KP + j] = tf(v.y);
                kb[(db + u + 2) * KP + j] = tf(v.z);
                kb[(db + u + 3) * KP + j] = tf(v.w);
            }
        };

        float S[2][2][4];
#pragma unroll
        for (int ma = 0; ma < 2; ma++)
#pragma unroll
            for (int na = 0; na < 2; na++)
#pragma unroll
                for (int c = 0; c < 4; c++) S[ma][na][c] = 0.f;

        // ---- scores: 9 d-chunks of 64, double-buffered ----
        loadK(0, KVs);
        __syncthreads();
        for (int dc = 0; dc < 9; dc++) {
            const float* kb = KVs + (dc & 1) * KBUF;
            if (dc < 8) loadK(dc + 1, KVs + ((dc + 1) & 1) * KBUF);
            const float* Qc = Qs + dc * 64;
#pragma unroll
            for (int kk = 0; kk < 8; kk++) {
                unsigned a[2][4], bq[2][2];
#pragma unroll
                for (int ma = 0; ma < 2; ma++) {
                    const float* p = Qc + (wr * 32 + ma * 16 + g) * QP + kk * 8 + tg;
                    a[ma][0] = __float_as_uint(p[0]);
                    a[ma][1] = __float_as_uint(p[8 * QP]);
                    a[ma][2] = __float_as_uint(p[4]);
                    a[ma][3] = __float_as_uint(p[8 * QP + 4]);
                }
#pragma unroll
                for (int na = 0; na < 2; na++) {
                    const float* p = kb + (kk * 8 + tg) * KP + wc * 16 + na * 8 + g;
                    bq[na][0] = __float_as_uint(p[0]);
                    bq[na][1] = __float_as_uint(p[4 * KP]);
                }
#pragma unroll
                for (int ma = 0; ma < 2; ma++)
#pragma unroll
                    for (int na = 0; na < 2; na++)
                        mma8(S[ma][na], a[ma], bq[na]);
            }
            __syncthreads();
        }

        // causal mask on diagonal tile
        if (kt == qt) {
#pragma unroll
            for (int ma = 0; ma < 2; ma++)
#pragma unroll
                for (int na = 0; na < 2; na++)
#pragma unroll
                    for (int ci = 0; ci < 4; ci++) {
                        int row = wr * 32 + ma * 16 + (ci >> 1) * 8 + g;
                        int col = wc * 16 + na * 8 + 2 * tg + (ci & 1);
                        if (col > row) S[ma][na][ci] = -1e30f;
                    }
        }

        // ---- row max ----
#pragma unroll
        for (int ma = 0; ma < 2; ma++)
#pragma unroll
            for (int hf = 0; hf < 2; hf++) {
                float v = fmaxf(fmaxf(S[ma][0][hf * 2], S[ma][0][hf * 2 + 1]),
                                fmaxf(S[ma][1][hf * 2], S[ma][1][hf * 2 + 1]));
                v = fmaxf(v, __shfl_xor_sync(0xffffffffu, v, 1));
                v = fmaxf(v, __shfl_xor_sync(0xffffffffu, v, 2));
                if (tg == 0)
                    Red[(wr * 32 + ma * 16 + hf * 8 + g) * 8 + wc] = v;
            }
        __syncthreads();
        if (tid < 64) {
            float mx = fmaxf(fmaxf(Red[tid * 8 + 0], Red[tid * 8 + 1]),
                             fmaxf(Red[tid * 8 + 2], Red[tid * 8 + 3]));
            float mo = msm[tid];
            float mn = fmaxf(mo, mx);
            msm[tid] = mn; mns[tid] = mn;
            fsm[tid] = __expf(mo - mn);
        }
        __syncthreads();

        // ---- exp, write P (tf32), partial sums, rescale O ----
#pragma unroll
        for (int ma = 0; ma < 2; ma++)
#pragma unroll
            for (int hf = 0; hf < 2; hf++) {
                int row = wr * 32 + ma * 16 + hf * 8 + g;
                float mn = mns[row];
                float s = 0.f;
#pragma unroll
                for (int na = 0; na < 2; na++) {
                    float p0 = __expf(S[ma][na][hf * 2 + 0] - mn);
                    float p1 = __expf(S[ma][na][hf * 2 + 1] - mn);
                    s += p0 + p1;
                    float2 pv; pv.x = tf(p0); pv.y = tf(p1);
                    *(float2*)(Ps + row * PP + wc * 16 + na * 8 + 2 * tg) = pv;
                }
                s += __shfl_xor_sync(0xffffffffu, s, 1);
                s += __shfl_xor_sync(0xffffffffu, s, 2);
                if (tg == 0) Red[row * 8 + 4 + wc] = s;
            }
#pragma unroll
        for (int ma = 0; ma < 2; ma++) {
            float f0 = fsm[wr * 32 + ma * 16 + g];
            float f1 = fsm[wr * 32 + ma * 16 + 8 + g];
#pragma unroll
            for (int na = 0; na < 16; na++) {
                O[ma][na][0] *= f0; O[ma][na][1] *= f0;
                O[ma][na][2] *= f1; O[ma][na][3] *= f1;
            }
        }
        __syncthreads();
        if (tid < 64)
            lsm[tid] = lsm[tid] * fsm[tid] +
                       Red[tid * 8 + 4] + Red[tid * 8 + 5] +
                       Red[tid * 8 + 6] + Red[tid * 8 + 7];

        // V chunk loader: 8 keys x 512, natural layout, into vb[s][v]
        auto loadV = [&](int cc, float* vb) {
#pragma unroll
            for (int it = 0; it < 4; it++) {
                int i4 = tid + it * 256;              // 0..1023 float4s
                int s = i4 >> 7, v4 = (i4 & 127) * 4;
                float4 v = *(const float4*)(ckvb + (size_t)(s0 + cc * 8 + s) * NLKV_ + v4);
                float4 o;
                o.x = tf(v.x); o.y = tf(v.y); o.z = tf(v.z); o.w = tf(v.w);
                *(float4*)(vb + s * VP + v4) = o;
            }
        };

        // ---- PV: 8 s-chunks of 8 keys, double-buffered ----
        loadV(0, KVs);
        __syncthreads();
        for (int cc = 0; cc < 8; cc++) {
            const float* vb = KVs + (cc & 1) * VBUF;
            if (cc < 7) loadV(cc + 1, KVs + ((cc + 1) & 1) * VBUF);
            unsigned a0[4], a1[4];
            int sc = cc * 8 + tg;
            {
                const float* p = Ps + (wr * 32 + g) * PP + sc;
                a0[0] = __float_as_uint(p[0]);
                a0[1] = __float_as_uint(p[8 * PP]);
                a0[2] = __float_as_uint(p[4]);
                a0[3] = __float_as_uint(p[8 * PP + 4]);
            }
            {
                const float* p = Ps + (wr * 32 + 16 + g) * PP + sc;
                a1[0] = __float_as_uint(p[0]);
                a1[1] = __float_as_uint(p[8 * PP]);
                a1[2] = __float_as_uint(p[4]);
                a1[3] = __float_as_uint(p[8 * PP + 4]);
            }
#pragma unroll
            for (int na = 0; na < 16; na++) {
                const float* p = vb + tg * VP + wc * 128 + na * 8 + g;
                unsigned bq[2];
                bq[0] = __float_as_uint(p[0]);
                bq[1] = __float_as_uint(p[4 * VP]);
                mma8(O[0][na], a0, bq);
                mma8(O[1][na], a1, bq);
            }
            __syncthreads();
        }
    }

    // ---- epilogue: normalize and write ctx ----
#pragma unroll
    for (int ma = 0; ma < 2; ma++)
#pragma unroll
        for (int hf = 0; hf < 2; hf++) {
            int row = wr * 32 + ma * 16 + hf * 8 + g;
            float inv = 1.0f / lsm[row];
            float* orow = ctx + ((size_t)(b * NH_ + h) * TT + t0 + row) * NLKV_;
#pragma unroll
            for (int na = 0; na < 16; na++) {
                float2 o;
                o.x = O[ma][na][hf * 2]     * inv;
                o.y = O[ma][na][hf * 2 + 1] * inv;
                *(float2*)(orow + wc * 128 + na * 8 + 2 * tg) = o;
            }
        }
}

// ---------------- launch ----------------
extern "C" void kernel_launch(void* const* d_in, const int* in_sizes, int n_in,
                              void* d_out, int out_size)
{
    (void)in_sizes; (void)n_in; (void)out_size;
    const float* x    = (const float*)d_in[0];
    const float* cs   = (const float*)d_in[1];
    const float* sn   = (const float*)d_in[2];
    const float* W_dq = (const float*)d_in[3];
    const float* W_uq = (const float*)d_in[4];
    const float* W_dkv= (const float*)d_in[5];
    const float* W_uk = (const float*)d_in[6];
    const float* W_uv = (const float*)d_in[7];
    const float* W_qr = (const float*)d_in[8];
    const float* W_kr = (const float*)d_in[9];
    const float* W_o  = (const float*)d_in[10];
    float* y = (float*)d_out;

    float *cq, *ckv, *keff, *vtmp, *qlat, *qr, *kr, *ctx;
    cudaGetSymbolAddress((void**)&cq,   d_cq);
    cudaGetSymbolAddress((void**)&ckv,  d_ckv);
    cudaGetSymbolAddress((void**)&keff, d_keff);
    cudaGetSymbolAddress((void**)&vtmp, d_vtmp);
    cudaGetSymbolAddress((void**)&qlat, d_qlat);
    cudaGetSymbolAddress((void**)&qr,   d_qr);
    cudaGetSymbolAddress((void**)&kr,   d_kr);
    cudaGetSymbolAddress((void**)&ctx,  d_ctx);

    const int MT = BB * TT;   // 4096

    // 1) c_q = x @ W_dq^T   (tf32)
    tgemm<<<dim3(NLQ_/128, MT/128, 1), 256>>>(x, W_dq, cq,
        MT, NLQ_, CC,  CC,1, 0,0,  CC,1, 0,0,  NLQ_, 0,0, 1);

    // 2) c_kv = x @ W_dkv^T   (tf32)
    tgemm<<<dim3(NLKV_/128, MT/128, 1), 256>>>(x, W_dkv, ckv,
        MT, NLKV_, CC,  CC,1, 0,0,  CC,1, 0,0,  NLKV_, 0,0, 1);

    // 3) k_eff  (tf32)
    tgemm<<<dim3(NLKV_/128, NLQ_/128, NH_), 256>>>(W_uq, W_uk, keff,
        NLQ_, NLKV_, HS_,
        CC,1, 0,(long long)HS_,
        1,(long long)NLKV_, 0,(long long)HS_*NLKV_,
        NLKV_, 0,(long long)NLQ_*NLKV_, NH_);

    // 4) v_tmp = W_uv^T @ W_o^T   (tf32)
    tgemm<<<dim3(CC/128, NLKV_/128, 1), 256>>>(W_uv, W_o, vtmp,
        NLKV_, CC, CC,
        1,(long long)NLKV_, 0,0,
        CC,1, 0,0,
        CC, 0,0, 1);

    // 5) qr_lin = c_q @ W_qr^T   (tf32)
    tgemm<<<dim3((NH_*DHR_)/128, MT/128, 1), 256>>>(cq, W_qr, qr,
        MT, NH_*DHR_, NLQ_,  NLQ_,1, 0,0,  NLQ_,1, 0,0,  NH_*DHR_, 0,0, 1);

    // 6) kr_lin = x @ W_kr^T   (fp32, small: N=64)
    sgemm_g<<<dim3(1, MT/64, 1), 256>>>(x, W_kr, kr,
        MT, DHR_, CC,  CC,1, 0,0,  CC,1, 0,0,  DHR_, 0,0, 1);

    // 7) RoPE (in place)
    rope_qr_kernel<<<(BB*TT*NH_*32 + 255)/256, 256>>>(qr, cs, sn);
    rope_kr_kernel<<<(BB*TT*32 + 255)/256, 256>>>(kr, cs, sn);

    // 8) q_lat = c_q @ k_eff   (tf32, large)
    tgemm<<<dim3(NLKV_/128, TT/128, BB*NH_), 256>>>(cq, keff, qlat,
        TT, NLKV_, NLQ_,
        NLQ_,1, (long long)TT*NLQ_, 0,
        1,(long long)NLKV_, 0,(long long)NLQ_*NLKV_,
        NLKV_, (long long)NH_*TT*NLKV_, (long long)TT*NLKV_, NH_);

    // 9) flash attention core (tf32 tensor cores, double-buffered) -> ctx
    static const size_t smem_bytes = (size_t)FTC_FLOATS * sizeof(float);
    cudaFuncSetAttribute(flash_tc, cudaFuncAttributeMaxDynamicSharedMemorySize,
                         (int)smem_bytes);
    flash_tc<<<dim3(TT/64, NH_, BB), 256, smem_bytes>>>(qlat, qr, ckv, kr, ctx);

    // 10) y = ctx @ v_eff   (tf32; N=128 per head)
    tgemm<<<dim3(HS_/128, TT/128, BB*NH_), 256>>>(ctx, vtmp, y,
        TT, HS_, NLKV_,
        NLKV_,1, (long long)NH_*TT*NLKV_, (long long)TT*NLKV_,
        1,(long long)CC, 0,(long long)HS_,
        CC, (long long)TT*CC, (long long)HS_, NH_);
}

// round 14
// speedup vs baseline: 2.7203x; 1.0298x over previous
#include <cuda_runtime.h>
#include <math.h>

// Problem constants
#define BB   2
#define TT   2048
#define CC   2048
#define NH_  16
#define HS_  128
#define NLQ_ 512
#define NLKV_ 512
#define DHR_ 64

// ---------------- scratch buffers ----------------
__device__ __align__(16) float d_cq  [(size_t)BB*TT*NLQ_];
__device__ __align__(16) float d_ckv [(size_t)BB*TT*NLKV_];
__device__ __align__(16) float d_keff[(size_t)NH_*NLQ_*NLKV_];
__device__ __align__(16) float d_vtmp[(size_t)NLKV_*CC];
__device__ __align__(16) float d_qlat[(size_t)BB*NH_*TT*NLKV_];
__device__ __align__(16) float d_qr  [(size_t)BB*TT*NH_*DHR_];
__device__ __align__(16) float d_kr  [(size_t)BB*TT*DHR_];
__device__ __align__(16) float d_ctx [(size_t)BB*NH_*TT*NLKV_];

// ---------------- tf32 helpers ----------------
__device__ __forceinline__ float tf(float x) {
    unsigned r; asm("cvt.rna.tf32.f32 %0, %1;" : "=r"(r) : "f"(x));
    return __uint_as_float(r);
}
__device__ __forceinline__ void mma8(float d[4], const unsigned a[4], const unsigned b[2]) {
    asm volatile(
        "mma.sync.aligned.m16n8k8.row.col.f32.tf32.tf32.f32 "
        "{%0,%1,%2,%3}, {%4,%5,%6,%7}, {%8,%9}, {%0,%1,%2,%3};\n"
        : "+f"(d[0]), "+f"(d[1]), "+f"(d[2]), "+f"(d[3])
        : "r"(a[0]), "r"(a[1]), "r"(a[2]), "r"(a[3]), "r"(b[0]), "r"(b[1]));
}

// ---------------- generic strided fp32 SGEMM (small leftovers only) ----------------
__global__ __launch_bounds__(256) void sgemm_g(
    const float* __restrict__ A, const float* __restrict__ B, float* __restrict__ C,
    int M, int N, int K,
    long long sAm, long long sAk, long long sAb, long long sAh,
    long long sBn, long long sBk, long long sBb, long long sBh,
    long long sCm, long long sCb, long long sCh, int H)
{
    __shared__ float As[16][68];
    __shared__ float Bs[16][68];

    int z = blockIdx.z;
    int bb = z / H, hh = z - bb * H;
    A += (size_t)bb * sAb + (size_t)hh * sAh;
    B += (size_t)bb * sBb + (size_t)hh * sBh;
    C += (size_t)bb * sCb + (size_t)hh * sCh;

    int m0 = blockIdx.y * 64, n0 = blockIdx.x * 64;
    int tid = threadIdx.x;
    int tx = tid & 15, ty = tid >> 4;

    float acc[4][4];
#pragma unroll
    for (int i = 0; i < 4; i++)
#pragma unroll
        for (int j = 0; j < 4; j++) acc[i][j] = 0.f;

    for (int k0 = 0; k0 < K; k0 += 16) {
#pragma unroll
        for (int u = 0; u < 4; u++) {
            int idx = tid * 4 + u;
            int m = idx >> 4, kk = idx & 15;
            int gm = m0 + m, gk = k0 + kk;
            As[kk][m] = (gm < M && gk < K) ? A[(size_t)gm * sAm + (size_t)gk * sAk] : 0.f;
            int gn = n0 + m;
            Bs[kk][m] = (gn < N && gk < K) ? B[(size_t)gn * sBn + (size_t)gk * sBk] : 0.f;
        }
        __syncthreads();
#pragma unroll
        for (int kk = 0; kk < 16; kk++) {
            float4 av = *(const float4*)&As[kk][ty << 2];
            float4 bv = *(const float4*)&Bs[kk][tx << 2];
            float a[4] = {av.x, av.y, av.z, av.w};
            float b[4] = {bv.x, bv.y, bv.z, bv.w};
#pragma unroll
            for (int i = 0; i < 4; i++)
#pragma unroll
                for (int j = 0; j < 4; j++)
                    acc[i][j] = fmaf(a[i], b[j], acc[i][j]);
        }
        __syncthreads();
    }
#pragma unroll
    for (int i = 0; i < 4; i++) {
        int gm = m0 + (ty << 2) + i;
        if (gm >= M) continue;
#pragma unroll
        for (int j = 0; j < 4; j++) {
            int gn = n0 + (tx << 2) + j;
            if (gn < N) C[(size_t)gm * sCm + gn] = acc[i][j];
        }
    }
}

// ---------------- generic strided tf32 tensor GEMM (double-buffered, 2 CTA/SM) ----------------
// 128x128 block tile, 256 threads, warp grid 2(m) x 4(n), warp tile 64x32.
// REQUIRES: M % 128 == 0, N % 128 == 0, K % 16 == 0.
__global__ __launch_bounds__(256, 2) void tgemm(
    const float* __restrict__ A, const float* __restrict__ B, float* __restrict__ C,
    int M, int N, int K,
    long long sAm, long long sAk, long long sAb, long long sAh,
    long long sBn, long long sBk, long long sBb, long long sBh,
    long long sCm, long long sCb, long long sCh, int H)
{
    __shared__ float As[2][16][136];   // [buf][k][m]
    __shared__ float Bs[2][16][136];   // [buf][k][n]

    int z = blockIdx.z;
    int bb = z / H, hh = z - bb * H;
    A += (size_t)bb * sAb + (size_t)hh * sAh;
    B += (size_t)bb * sBb + (size_t)hh * sBh;
    C += (size_t)bb * sCb + (size_t)hh * sCh;

    int m0 = blockIdx.y * 128, n0 = blockIdx.x * 128;
    int tid = threadIdx.x, lane = tid & 31, w = tid >> 5;
    int g = lane >> 2, tg = lane & 3;
    int wr = w & 1, wc = w >> 1;

    float acc[4][4][4];
#pragma unroll
    for (int i = 0; i < 4; i++)
#pragma unroll
        for (int j = 0; j < 4; j++)
#pragma unroll
            for (int c = 0; c < 4; c++) acc[i][j][c] = 0.f;

    float ra[8], rb[8];

    auto fetchA = [&](int kof) {
        if (sAk == 1) {
            int m = tid >> 1, kk = (tid & 1) * 8;
            const float* p = A + (size_t)(m0 + m) * sAm + kof + kk;
            float4 v0 = *(const float4*)p;
            float4 v1 = *(const float4*)(p + 4);
            ra[0] = v0.x; ra[1] = v0.y; ra[2] = v0.z; ra[3] = v0.w;
            ra[4] = v1.x; ra[5] = v1.y; ra[6] = v1.z; ra[7] = v1.w;
        } else {
#pragma unroll
            for (int u = 0; u < 8; u++) {
                int idx = tid + u * 256;
                int kk = idx >> 7, m = idx & 127;
                ra[u] = A[(size_t)(m0 + m) * sAm + (size_t)(kof + kk) * sAk];
            }
        }
    };
    auto storeA = [&](int bf) {
        if (sAk == 1) {
            int m = tid >> 1, kk = (tid & 1) * 8;
#pragma unroll
            for (int u = 0; u < 8; u++) As[bf][kk + u][m] = tf(ra[u]);
        } else {
#pragma unroll
            for (int u = 0; u < 8; u++) {
                int idx = tid + u * 256;
                int kk = idx >> 7, m = idx & 127;
                As[bf][kk][m] = tf(ra[u]);
            }
        }
    };
    auto fetchB = [&](int kof) {
        if (sBk == 1) {
            int n = tid >> 1, kk = (tid & 1) * 8;
            const float* p = B + (size_t)(n0 + n) * sBn + kof + kk;
            float4 v0 = *(const float4*)p;
            float4 v1 = *(const float4*)(p + 4);
            rb[0] = v0.x; rb[1] = v0.y; rb[2] = v0.z; rb[3] = v0.w;
            rb[4] = v1.x; rb[5] = v1.y; rb[6] = v1.z; rb[7] = v1.w;
        } else {
#pragma unroll
            for (int u = 0; u < 8; u++) {
                int idx = tid + u * 256;
                int kk = idx >> 7, n = idx & 127;
                rb[u] = B[(size_t)(n0 + n) * sBn + (size_t)(kof + kk) * sBk];
            }
        }
    };
    auto storeB = [&](int bf) {
        if (sBk == 1) {
            int n = tid >> 1, kk = (tid & 1) * 8;
#pragma unroll
            for (int u = 0; u < 8; u++) Bs[bf][kk + u][n] = tf(rb[u]);
        } else {
#pragma unroll
            for (int u = 0; u < 8; u++) {
                int idx = tid + u * 256;
                int kk = idx >> 7, n = idx & 127;
                Bs[bf][kk][n] = tf(rb[u]);
            }
        }
    };

    const int KT = K >> 4;
    fetchA(0); fetchB(0);
    storeA(0); storeB(0);
    __syncthreads();

    for (int kt = 0; kt < KT; kt++) {
        int cur = kt & 1;
        if (kt + 1 < KT) { fetchA((kt + 1) << 4); fetchB((kt + 1) << 4); }
#pragma unroll
        for (int kk2 = 0; kk2 < 2; kk2++) {
            int kb = kk2 * 8 + tg;
            unsigned a[4][4], bq[4][2];
#pragma unroll
            for (int ma = 0; ma < 4; ma++) {
                const float* p = &As[cur][kb][wr * 64 + ma * 16 + g];
                a[ma][0] = __float_as_uint(p[0]);
                a[ma][1] = __float_as_uint(p[8]);
                a[ma][2] = __float_as_uint(p[4 * 136]);
                a[ma][3] = __float_as_uint(p[4 * 136 + 8]);
            }
#pragma unroll
            for (int na = 0; na < 4; na++) {
                const float* p = &Bs[cur][kb][wc * 32 + na * 8 + g];
                bq[na][0] = __float_as_uint(p[0]);
                bq[na][1] = __float_as_uint(p[4 * 136]);
            }
#pragma unroll
            for (int ma = 0; ma < 4; ma++)
#pragma unroll
                for (int na = 0; na < 4; na++)
                    mma8(acc[ma][na], a[ma], bq[na]);
        }
        if (kt + 1 < KT) { storeA(cur ^ 1); storeB(cur ^ 1); }
        __syncthreads();
    }
#pragma unroll
    for (int ma = 0; ma < 4; ma++)
#pragma unroll
        for (int hf = 0; hf < 2; hf++) {
            int gm = m0 + wr * 64 + ma * 16 + hf * 8 + g;
#pragma unroll
            for (int na = 0; na < 4; na++) {
                int gn = n0 + wc * 32 + na * 8 + 2 * tg;
                float2 o;
                o.x = acc[ma][na][hf * 2];
                o.y = acc[ma][na][hf * 2 + 1];
                *(float2*)&C[(size_t)gm * sCm + gn] = o;
            }
        }
}

// ---------------- RoPE kernels (in-place) ----------------
__global__ void rope_qr_kernel(float* __restrict__ qr,
                               const float* __restrict__ cs, const float* __restrict__ sn)
{
    int idx = blockIdx.x * blockDim.x + threadIdx.x;
    if (idx >= BB * TT * NH_ * 32) return;
    int i  = idx & 31;
    int h  = (idx >> 5) & 15;
    int bt = idx >> 9;
    int t  = bt & (TT - 1);
    float c = cs[t * 32 + i], s = sn[t * 32 + i];
    size_t base = (size_t)bt * (NH_ * DHR_) + h * DHR_ + 2 * i;
    float re = qr[base], im = qr[base + 1];
    qr[base]     = re * c - im * s;
    qr[base + 1] = re * s + im * c;
}

__global__ void rope_kr_kernel(float* __restrict__ kr,
                               const float* __restrict__ cs, const float* __restrict__ sn)
{
    int idx = blockIdx.x * blockDim.x + threadIdx.x;
    if (idx >= BB * TT * 32) return;
    int i  = idx & 31;
    int bt = idx >> 5;
    int t  = bt & (TT - 1);
    float c = cs[t * 32 + i], s = sn[t * 32 + i];
    size_t base = (size_t)bt * DHR_ + 2 * i;
    float re = kr[base], im = kr[base + 1];
    kr[base]     = re * c - im * s;
    kr[base + 1] = re * s + im * c;
}

// ---------------- tf32 tensor-core flash attention v3 ----------------
// Q streamed per d-chunk (double-buffered), K double-buffered, V tile RESIDENT.
// PV phase has zero internal barriers. 64-query tiles, warp grid 2(m) x 4(n).
#define QCP 68              // Q chunk pitch (4 mod 32)
#define PP  68              // Ps pitch (4 mod 32)
#define KCP 72              // K chunk pitch (8 mod 32)
#define VPP 520             // V tile pitch (8 mod 32)
#define QBUF (64 * QCP)     // 4352
#define KBUF (64 * KCP)     // 4608
#define FTC_FLOATS (2*QBUF + 2*KBUF + 64*VPP + 64*PP + 64*8 + 4*64)   // 56320 fl = 225280 B

__global__ __launch_bounds__(256, 1) void flash_tc(
    const float* __restrict__ qlat, const float* __restrict__ qr,
    const float* __restrict__ ckv,  const float* __restrict__ kr,
    float* __restrict__ ctx)
{
    extern __shared__ float smx[];
    float* Qb  = smx;                 // 2 x [64][QCP]
    float* Kb  = Qb + 2 * QBUF;       // 2 x [64][KCP]  (layout [d][key])
    float* Vs  = Kb + 2 * KBUF;       // [64][VPP]      (layout [key][d], resident)
    float* Ps  = Vs + 64 * VPP;       // [64][PP]
    float* Red = Ps + 64 * PP;        // [64][8]
    float* msm = Red + 64 * 8;
    float* lsm = msm + 64;
    float* fsm = lsm + 64;
    float* mns = fsm + 64;

    int qt = blockIdx.x, h = blockIdx.y, b = blockIdx.z;
    int t0 = qt * 64;
    int tid = threadIdx.x, lane = tid & 31, w = tid >> 5;
    int g = lane >> 2, tg = lane & 3;
    int wr = w & 1, wc = w >> 1;
    const float scale = rsqrtf((float)(HS_ + DHR_));

    const float* qlatp = qlat + ((size_t)(b * NH_ + h) * TT + t0) * NLKV_;
    const float* qrp   = qr   + ((size_t)b * TT + t0) * (NH_ * DHR_) + h * DHR_;
    const float* ckvb  = ckv  + (size_t)b * TT * NLKV_;
    const float* krb   = kr   + (size_t)b * TT * DHR_;

    float kst[16], vst[16];

    // K chunk dc (0..8) of key-tile at s0v, transposed into kb[d][key]
    auto fetchK = [&](int s0v, int dc) {
        int j = tid >> 2;
        int db = (tid & 3) * 16;
        const float* src = (dc < 8)
            ? (ckvb + (size_t)(s0v + j) * NLKV_ + dc * 64 + db)
            : (krb  + (size_t)(s0v + j) * DHR_ + db);
#pragma unroll
        for (int u = 0; u < 16; u += 4) {
            float4 v = *(const float4*)(src + u);
            kst[u] = v.x; kst[u+1] = v.y; kst[u+2] = v.z; kst[u+3] = v.w;
        }
    };
    auto storeK = [&](float* kb) {
        int j = tid >> 2;
        int db = (tid & 3) * 16;
#pragma unroll
        for (int u = 0; u < 16; u++) kb[(db + u) * KCP + j] = tf(kst[u]);
    };
    // V slice sl (0..7): 8 rows x 512 of the resident V tile
    auto fetchV = [&](int s0v, int sl) {
#pragma unroll
        for (int u = 0; u < 4; u++) {
            int i4 = tid + (sl * 4 + u) * 256;
            int r = i4 >> 7, c4 = (i4 & 127) * 4;
            float4 v = *(const float4*)(ckvb + (size_t)(s0v + r) * NLKV_ + c4);
            vst[u*4] = v.x; vst[u*4+1] = v.y; vst[u*4+2] = v.z; vst[u*4+3] = v.w;
        }
    };
    auto storeV = [&](int sl) {
#pragma unroll
        for (int u = 0; u < 4; u++) {
            int i4 = tid + (sl * 4 + u) * 256;
            int r = i4 >> 7, c4 = (i4 & 127) * 4;
            float* d = Vs + r * VPP + c4;
            d[0] = tf(vst[u*4]);   d[1] = tf(vst[u*4+1]);
            d[2] = tf(vst[u*4+2]); d[3] = tf(vst[u*4+3]);
        }
    };
    // Q chunk dc: direct load+store (L1/L2-hot; same data every key tile)
    auto loadQdir = [&](int dc, float* qb) {
#pragma unroll
        for (int u = 0; u < 4; u++) {
            int i4 = tid + u * 256;
            int r = i4 >> 4, c4 = (i4 & 15) * 4;
            float4 v;
            if (dc < 8) v = *(const float4*)(qlatp + (size_t)r * NLKV_ + dc * 64 + c4);
            else        v = *(const float4*)(qrp  + (size_t)r * (NH_ * DHR_) + c4);
            float4 o;
            o.x = tf(v.x * scale); o.y = tf(v.y * scale);
            o.z = tf(v.z * scale); o.w = tf(v.w * scale);
            *(float4*)(qb + r * QCP + c4) = o;
        }
    };

    if (tid < 64) { msm[tid] = -1e30f; lsm[tid] = 0.f; }

    float O[2][16][4];
#pragma unroll
    for (int ma = 0; ma < 2; ma++)
#pragma unroll
        for (int na = 0; na < 16; na++)
#pragma unroll
            for (int c = 0; c < 4; c++) O[ma][na][c] = 0.f;

    // prime chunk 0 of tile 0
    loadQdir(0, Qb);
    fetchK(0, 0);
    storeK(Kb);
    __syncthreads();

    for (int kt = 0; kt <= qt; kt++) {
        int s0 = kt * 64;
        float S[2][2][4];
#pragma unroll
        for (int ma = 0; ma < 2; ma++)
#pragma unroll
            for (int na = 0; na < 2; na++)
#pragma unroll
                for (int c = 0; c < 4; c++) S[ma][na][c] = 0.f;

        // ---- S phase: 9 d-chunks, Q+K double-buffered; V tile loads interleaved ----
        for (int dc = 0; dc < 9; dc++) {
            const float* qc = Qb + (dc & 1) * QBUF;
            const float* kc = Kb + (dc & 1) * KBUF;
            if (dc < 8) {
                fetchK(s0, dc + 1);
                fetchV(s0, dc);
                loadQdir(dc + 1, Qb + ((dc + 1) & 1) * QBUF);
            }
#pragma unroll
            for (int kk = 0; kk < 8; kk++) {
                unsigned a[2][4], bq[2][2];
#pragma unroll
                for (int ma = 0; ma < 2; ma++) {
                    const float* p = qc + (wr * 32 + ma * 16 + g) * QCP + kk * 8 + tg;
                    a[ma][0] = __float_as_uint(p[0]);
                    a[ma][1] = __float_as_uint(p[8 * QCP]);
                    a[ma][2] = __float_as_uint(p[4]);
                    a[ma][3] = __float_as_uint(p[8 * QCP + 4]);
                }
#pragma unroll
                for (int na = 0; na < 2; na++) {
                    const float* p = kc + (kk * 8 + tg) * KCP + wc * 16 + na * 8 + g;
                    bq[na][0] = __float_as_uint(p[0]);
                    bq[na][1] = __float_as_uint(p[4 * KCP]);
                }
#pragma unroll
                for (int ma = 0; ma < 2; ma++)
#pragma unroll
                    for (int na = 0; na < 2; na++)
                        mma8(S[ma][na], a[ma], bq[na]);
            }
            if (dc < 8) {
                storeK(Kb + ((dc + 1) & 1) * KBUF);
                storeV(dc);
            }
            __syncthreads();
        }

        // causal mask on diagonal tile
        if (kt == qt) {
#pragma unroll
            for (int ma = 0; ma < 2; ma++)
#pragma unroll
                for (int na = 0; na < 2; na++)
#pragma unroll
                    for (int ci = 0; ci < 4; ci++) {
                        int row = wr * 32 + ma * 16 + (ci >> 1) * 8 + g;
                        int col = wc * 16 + na * 8 + 2 * tg + (ci & 1);
                        if (col > row) S[ma][na][ci] = -1e30f;
                    }
        }

        // ---- row max ----
#pragma unroll
        for (int ma = 0; ma < 2; ma++)
#pragma unroll
            for (int hf = 0; hf < 2; hf++) {
                float v = fmaxf(fmaxf(S[ma][0][hf * 2], S[ma][0][hf * 2 + 1]),
                                fmaxf(S[ma][1][hf * 2], S[ma][1][hf * 2 + 1]));
                v = fmaxf(v, __shfl_xor_sync(0xffffffffu, v, 1));
                v = fmaxf(v, __shfl_xor_sync(0xffffffffu, v, 2));
                if (tg == 0)
                    Red[(wr * 32 + ma * 16 + hf * 8 + g) * 8 + wc] = v;
            }
        __syncthreads();
        if (tid < 64) {
            float mx = fmaxf(fmaxf(Red[tid * 8 + 0], Red[tid * 8 + 1]),
                             fmaxf(Red[tid * 8 + 2], Red[tid * 8 + 3]));
            float mo = msm[tid];
            float mn = fmaxf(mo, mx);
            msm[tid] = mn; mns[tid] = mn;
            fsm[tid] = __expf(mo - mn);
        }
        __syncthreads();

        // ---- exp, write P (tf32), partial sums, rescale O ----
#pragma unroll
        for (int ma = 0; ma < 2; ma++)
#pragma unroll
            for (int hf = 0; hf < 2; hf++) {
                int row = wr * 32 + ma * 16 + hf * 8 + g;
                float mn = mns[row];
                float s = 0.f;
#pragma unroll
                for (int na = 0; na < 2; na++) {
                    float p0 = __expf(S[ma][na][hf * 2 + 0] - mn);
                    float p1 = __expf(S[ma][na][hf * 2 + 1] - mn);
                    s += p0 + p1;
                    float2 pv; pv.x = tf(p0); pv.y = tf(p1);
                    *(float2*)(Ps + row * PP + wc * 16 + na * 8 + 2 * tg) = pv;
                }
                s += __shfl_xor_sync(0xffffffffu, s, 1);
                s += __shfl_xor_sync(0xffffffffu, s, 2);
                if (tg == 0) Red[row * 8 + 4 + wc] = s;
            }
#pragma unroll
        for (int ma = 0; ma < 2; ma++) {
            float f0 = fsm[wr * 32 + ma * 16 + g];
            float f1 = fsm[wr * 32 + ma * 16 + 8 + g];
#pragma unroll
            for (int na = 0; na < 16; na++) {
                O[ma][na][0] *= f0; O[ma][na][1] *= f0;
                O[ma][na][2] *= f1; O[ma][na][3] *= f1;
            }
        }
        __syncthreads();
        if (tid < 64)
            lsm[tid] = lsm[tid] * fsm[tid] +
                       Red[tid * 8 + 4] + Red[tid * 8 + 5] +
                       Red[tid * 8 + 6] + Red[tid * 8 + 7];

        // prefetch next tile's chunk 0 (overlaps the PV phase)
        bool pre = (kt < qt);
        if (pre) {
            loadQdir(0, Qb);
            fetchK(s0 + 64, 0);
        }

        // ---- PV: full 64-key resident V, zero internal barriers ----
#pragma unroll
        for (int kk = 0; kk < 8; kk++) {
            unsigned a0[4], a1[4];
            int sc = kk * 8 + tg;
            {
                const float* p = Ps + (wr * 32 + g) * PP + sc;
                a0[0] = __float_as_uint(p[0]);
                a0[1] = __float_as_uint(p[8 * PP]);
                a0[2] = __float_as_uint(p[4]);
                a0[3] = __float_as_uint(p[8 * PP + 4]);
            }
            {
                const float* p = Ps + (wr * 32 + 16 + g) * PP + sc;
                a1[0] = __float_as_uint(p[0]);
                a1[1] = __float_as_uint(p[8 * PP]);
                a1[2] = __float_as_uint(p[4]);
                a1[3] = __float_as_uint(p[8 * PP + 4]);
            }
#pragma unroll
            for (int na = 0; na < 16; na++) {
                const float* p = Vs + (kk * 8 + tg) * VPP + wc * 128 + na * 8 + g;
                unsigned bq[2];
                bq[0] = __float_as_uint(p[0]);
                bq[1] = __float_as_uint(p[4 * VPP]);
                mma8(O[0][na], a0, bq);
                mma8(O[1][na], a1, bq);
            }
        }
        if (pre) storeK(Kb);
        __syncthreads();
    }

    // ---- epilogue: normalize and write ctx ----
#pragma unroll
    for (int ma = 0; ma < 2; ma++)
#pragma unroll
        for (int hf = 0; hf < 2; hf++) {
            int row = wr * 32 + ma * 16 + hf * 8 + g;
            float inv = 1.0f / lsm[row];
            float* orow = ctx + ((size_t)(b * NH_ + h) * TT + t0 + row) * NLKV_;
#pragma unroll
            for (int na = 0; na < 16; na++) {
                float2 o;
                o.x = O[ma][na][hf * 2]     * inv;
                o.y = O[ma][na][hf * 2 + 1] * inv;
                *(float2*)(orow + wc * 128 + na * 8 + 2 * tg) = o;
            }
        }
}

// ---------------- launch ----------------
extern "C" void kernel_launch(void* const* d_in, const int* in_sizes, int n_in,
                              void* d_out, int out_size)
{
    (void)in_sizes; (void)n_in; (void)out_size;
    const float* x    = (const float*)d_in[0];
    const float* cs   = (const float*)d_in[1];
    const float* sn   = (const float*)d_in[2];
    const float* W_dq = (const float*)d_in[3];
    const float* W_uq = (const float*)d_in[4];
    const float* W_dkv= (const float*)d_in[5];
    const float* W_uk = (const float*)d_in[6];
    const float* W_uv = (const float*)d_in[7];
    const float* W_qr = (const float*)d_in[8];
    const float* W_kr = (const float*)d_in[9];
    const float* W_o  = (const float*)d_in[10];
    float* y = (float*)d_out;

    float *cq, *ckv, *keff, *vtmp, *qlat, *qr, *kr, *ctx;
    cudaGetSymbolAddress((void**)&cq,   d_cq);
    cudaGetSymbolAddress((void**)&ckv,  d_ckv);
    cudaGetSymbolAddress((void**)&keff, d_keff);
    cudaGetSymbolAddress((void**)&vtmp, d_vtmp);
    cudaGetSymbolAddress((void**)&qlat, d_qlat);
    cudaGetSymbolAddress((void**)&qr,   d_qr);
    cudaGetSymbolAddress((void**)&kr,   d_kr);
    cudaGetSymbolAddress((void**)&ctx,  d_ctx);

    const int MT = BB * TT;   // 4096

    // 1) c_q = x @ W_dq^T   (tf32)
    tgemm<<<dim3(NLQ_/128, MT/128, 1), 256>>>(x, W_dq, cq,
        MT, NLQ_, CC,  CC,1, 0,0,  CC,1, 0,0,  NLQ_, 0,0, 1);

    // 2) c_kv = x @ W_dkv^T   (tf32)
    tgemm<<<dim3(NLKV_/128, MT/128, 1), 256>>>(x, W_dkv, ckv,
        MT, NLKV_, CC,  CC,1, 0,0,  CC,1, 0,0,  NLKV_, 0,0, 1);

    // 3) k_eff  (tf32)
    tgemm<<<dim3(NLKV_/128, NLQ_/128, NH_), 256>>>(W_uq, W_uk, keff,
        NLQ_, NLKV_, HS_,
        CC,1, 0,(long long)HS_,
        1,(long long)NLKV_, 0,(long long)HS_*NLKV_,
        NLKV_, 0,(long long)NLQ_*NLKV_, NH_);

    // 4) v_tmp = W_uv^T @ W_o^T   (tf32)
    tgemm<<<dim3(CC/128, NLKV_/128, 1), 256>>>(W_uv, W_o, vtmp,
        NLKV_, CC, CC,
        1,(long long)NLKV_, 0,0,
        CC,1, 0,0,
        CC, 0,0, 1);

    // 5) qr_lin = c_q @ W_qr^T   (tf32)
    tgemm<<<dim3((NH_*DHR_)/128, MT/128, 1), 256>>>(cq, W_qr, qr,
        MT, NH_*DHR_, NLQ_,  NLQ_,1, 0,0,  NLQ_,1, 0,0,  NH_*DHR_, 0,0, 1);

    // 6) kr_lin = x @ W_kr^T   (fp32, small: N=64)
    sgemm_g<<<dim3(1, MT/64, 1), 256>>>(x, W_kr, kr,
        MT, DHR_, CC,  CC,1, 0,0,  CC,1, 0,0,  DHR_, 0,0, 1);

    // 7) RoPE (in place)
    rope_qr_kernel<<<(BB*TT*NH_*32 + 255)/256, 256>>>(qr, cs, sn);
    rope_kr_kernel<<<(BB*TT*32 + 255)/256, 256>>>(kr, cs, sn);

    // 8) q_lat = c_q @ k_eff   (tf32, large)
    tgemm<<<dim3(NLKV_/128, TT/128, BB*NH_), 256>>>(cq, keff, qlat,
        TT, NLKV_, NLQ_,
        NLQ_,1, (long long)TT*NLQ_, 0,
        1,(long long)NLKV_, 0,(long long)NLQ_*NLKV_,
        NLKV_, (long long)NH_*TT*NLKV_, (long long)TT*NLKV_, NH_);

    // 9) flash attention core v3 -> ctx
    static const size_t smem_bytes = (size_t)FTC_FLOATS * sizeof(float);
    cudaFuncSetAttribute(flash_tc, cudaFuncAttributeMaxDynamicSharedMemorySize,
                         (int)smem_bytes);
    flash_tc<<<dim3(TT/64, NH_, BB), 256, smem_bytes>>>(qlat, qr, ckv, kr, ctx);

    // 10) y = ctx @ v_eff   (tf32; N=128 per head)
    tgemm<<<dim3(HS_/128, TT/128, BB*NH_), 256>>>(ctx, vtmp, y,
        TT, HS_, NLKV_,
        NLKV_,1, (long long)NH_*TT*NLKV_, (long long)TT*NLKV_,
        1,(long long)CC, 0,(long long)HS_,
        CC, (long long)TT*CC, (long long)HS_, NH_);
}

// round 15
// speedup vs baseline: 2.7450x; 1.0091x over previous
#include <cuda_runtime.h>
#include <math.h>

// Problem constants
#define BB   2
#define TT   2048
#define CC   2048
#define NH_  16
#define HS_  128
#define NLQ_ 512
#define NLKV_ 512
#define DHR_ 64

// ---------------- scratch buffers ----------------
__device__ __align__(16) float d_cq  [(size_t)BB*TT*NLQ_];
__device__ __align__(16) float d_ckv [(size_t)BB*TT*NLKV_];
__device__ __align__(16) float d_keff[(size_t)NH_*NLQ_*NLKV_];
__device__ __align__(16) float d_vtmp[(size_t)NLKV_*CC];
__device__ __align__(16) float d_qlat[(size_t)BB*NH_*TT*NLKV_];
__device__ __align__(16) float d_qr  [(size_t)BB*TT*NH_*DHR_];
__device__ __align__(16) float d_kr  [(size_t)BB*TT*DHR_];
__device__ __align__(16) float d_ctx [(size_t)BB*NH_*TT*NLKV_];

// ---------------- tf32 / async helpers ----------------
__device__ __forceinline__ float tf(float x) {
    unsigned r; asm("cvt.rna.tf32.f32 %0, %1;" : "=r"(r) : "f"(x));
    return __uint_as_float(r);
}
__device__ __forceinline__ unsigned tfu(float x) {
    unsigned r; asm("cvt.rna.tf32.f32 %0, %1;" : "=r"(r) : "f"(x));
    return r;
}
__device__ __forceinline__ void mma8(float d[4], const unsigned a[4], const unsigned b[2]) {
    asm volatile(
        "mma.sync.aligned.m16n8k8.row.col.f32.tf32.tf32.f32 "
        "{%0,%1,%2,%3}, {%4,%5,%6,%7}, {%8,%9}, {%0,%1,%2,%3};\n"
        : "+f"(d[0]), "+f"(d[1]), "+f"(d[2]), "+f"(d[3])
        : "r"(a[0]), "r"(a[1]), "r"(a[2]), "r"(a[3]), "r"(b[0]), "r"(b[1]));
}
__device__ __forceinline__ void cp16(unsigned d, const float* s) {
    asm volatile("cp.async.ca.shared.global [%0], [%1], 16;" :: "r"(d), "l"(s));
}
__device__ __forceinline__ void cp_commit() { asm volatile("cp.async.commit_group;"); }
__device__ __forceinline__ void cp_wait2()  { asm volatile("cp.async.wait_group 2;"); }

// ---------------- generic strided fp32 SGEMM (small leftovers only) ----------------
__global__ __launch_bounds__(256) void sgemm_g(
    const float* __restrict__ A, const float* __restrict__ B, float* __restrict__ C,
    int M, int N, int K,
    long long sAm, long long sAk, long long sAb, long long sAh,
    long long sBn, long long sBk, long long sBb, long long sBh,
    long long sCm, long long sCb, long long sCh, int H)
{
    __shared__ float As[16][68];
    __shared__ float Bs[16][68];

    int z = blockIdx.z;
    int bb = z / H, hh = z - bb * H;
    A += (size_t)bb * sAb + (size_t)hh * sAh;
    B += (size_t)bb * sBb + (size_t)hh * sBh;
    C += (size_t)bb * sCb + (size_t)hh * sCh;

    int m0 = blockIdx.y * 64, n0 = blockIdx.x * 64;
    int tid = threadIdx.x;
    int tx = tid & 15, ty = tid >> 4;

    float acc[4][4];
#pragma unroll
    for (int i = 0; i < 4; i++)
#pragma unroll
        for (int j = 0; j < 4; j++) acc[i][j] = 0.f;

    for (int k0 = 0; k0 < K; k0 += 16) {
#pragma unroll
        for (int u = 0; u < 4; u++) {
            int idx = tid * 4 + u;
            int m = idx >> 4, kk = idx & 15;
            int gm = m0 + m, gk = k0 + kk;
            As[kk][m] = (gm < M && gk < K) ? A[(size_t)gm * sAm + (size_t)gk * sAk] : 0.f;
            int gn = n0 + m;
            Bs[kk][m] = (gn < N && gk < K) ? B[(size_t)gn * sBn + (size_t)gk * sBk] : 0.f;
        }
        __syncthreads();
#pragma unroll
        for (int kk = 0; kk < 16; kk++) {
            float4 av = *(const float4*)&As[kk][ty << 2];
            float4 bv = *(const float4*)&Bs[kk][tx << 2];
            float a[4] = {av.x, av.y, av.z, av.w};
            float b[4] = {bv.x, bv.y, bv.z, bv.w};
#pragma unroll
            for (int i = 0; i < 4; i++)
#pragma unroll
                for (int j = 0; j < 4; j++)
                    acc[i][j] = fmaf(a[i], b[j], acc[i][j]);
        }
        __syncthreads();
    }
#pragma unroll
    for (int i = 0; i < 4; i++) {
        int gm = m0 + (ty << 2) + i;
        if (gm >= M) continue;
#pragma unroll
        for (int j = 0; j < 4; j++) {
            int gn = n0 + (tx << 2) + j;
            if (gn < N) C[(size_t)gm * sCm + gn] = acc[i][j];
        }
    }
}

// ---------------- tf32 tensor GEMM, 4-stage cp.async pipeline ----------------
// Template: AKC = A k-contiguous (sAk==1); else assumes sAm==1 (m-contiguous).
//           BKC = B k-contiguous (sBk==1); else assumes sBn==1 (n-contiguous).
// 128x128 block, 256 threads, warp grid 2(m) x 4(n), warp tile 64x32.
// smem holds RAW fp32; cvt.rna.tf32 applied at fragment load (identical bits
// to converting at store). REQUIRES M%128==0, N%128==0, K%16==0, K>=48.
template<int AKC, int BKC>
__global__ __launch_bounds__(256, 2) void tgemm_t(
    const float* __restrict__ A, const float* __restrict__ B, float* __restrict__ C,
    int M, int N, int K,
    long long sAm, long long sAk, long long sAb, long long sAh,
    long long sBn, long long sBk, long long sBb, long long sBh,
    long long sCm, long long sCb, long long sCh, int H)
{
    extern __shared__ float smp[];
    constexpr int ASZ = AKC ? 128 * 20 : 16 * 136;   // floats per A stage
    constexpr int BSZ = BKC ? 128 * 20 : 16 * 136;
    constexpr int STG = ASZ + BSZ;

    int z = blockIdx.z;
    int bb = z / H, hh = z - bb * H;
    A += (size_t)bb * sAb + (size_t)hh * sAh;
    B += (size_t)bb * sBb + (size_t)hh * sBh;
    C += (size_t)bb * sCb + (size_t)hh * sCh;

    int m0 = blockIdx.y * 128, n0 = blockIdx.x * 128;
    int tid = threadIdx.x, lane = tid & 31, w = tid >> 5;
    int g = lane >> 2, tg = lane & 3;
    int wr = w & 1, wc = w >> 1;

    unsigned sbase = (unsigned)__cvta_generic_to_shared(smp);

    float acc[4][4][4];
#pragma unroll
    for (int i = 0; i < 4; i++)
#pragma unroll
        for (int j = 0; j < 4; j++)
#pragma unroll
            for (int c = 0; c < 4; c++) acc[i][j][c] = 0.f;

    auto issue = [&](int s, int kof) {
        if (AKC) {   // A[m][k] k-contig -> Am[m][20]
            int m = tid >> 1, h2 = (tid & 1) * 8;
            const float* gp = A + (size_t)(m0 + m) * sAm + kof + h2;
            unsigned d = sbase + (unsigned)((s * STG + m * 20 + h2) * 4);
            cp16(d, gp); cp16(d + 16, gp + 4);
        } else {     // m-contig (sAm==1) -> As[k][136]
            int kk = tid & 15, ms = (tid >> 4) * 8;
            const float* gp = A + (size_t)(m0 + ms) + (size_t)(kof + kk) * sAk;
            unsigned d = sbase + (unsigned)((s * STG + kk * 136 + ms) * 4);
            cp16(d, gp); cp16(d + 16, gp + 4);
        }
        if (BKC) {   // B[n][k] k-contig -> Bn[n][20]
            int n = tid >> 1, h2 = (tid & 1) * 8;
            const float* gp = B + (size_t)(n0 + n) * sBn + kof + h2;
            unsigned d = sbase + (unsigned)((s * STG + ASZ + n * 20 + h2) * 4);
            cp16(d, gp); cp16(d + 16, gp + 4);
        } else {     // n-contig (sBn==1) -> Bs[k][136]
            int kk = tid & 15, ns = (tid >> 4) * 8;
            const float* gp = B + (size_t)(n0 + ns) + (size_t)(kof + kk) * sBk;
            unsigned d = sbase + (unsigned)((s * STG + ASZ + kk * 136 + ns) * 4);
            cp16(d, gp); cp16(d + 16, gp + 4);
        }
    };

    const int KT = K >> 4;
    issue(0, 0);  cp_commit();
    issue(1, 16); cp_commit();
    issue(2, 32); cp_commit();
    cp_wait2();
    __syncthreads();

    for (int kt = 0; kt < KT; kt++) {
        int s = kt & 3;
        const float* As_ = smp + s * STG;
        const float* Bs_ = smp + s * STG + ASZ;
#pragma unroll
        for (int kk2 = 0; kk2 < 2; kk2++) {
            int kb = kk2 * 8 + tg;
            unsigned a[4][4], bq[4][2];
#pragma unroll
            for (int ma = 0; ma < 4; ma++) {
                int r = wr * 64 + ma * 16 + g;
                if (AKC) {
                    const float* p = As_ + r * 20 + kb;
                    a[ma][0] = tfu(p[0]);        a[ma][1] = tfu(p[8 * 20]);
                    a[ma][2] = tfu(p[4]);        a[ma][3] = tfu(p[8 * 20 + 4]);
                } else {
                    const float* p = As_ + kb * 136 + r;
                    a[ma][0] = tfu(p[0]);        a[ma][1] = tfu(p[8]);
                    a[ma][2] = tfu(p[4 * 136]);  a[ma][3] = tfu(p[4 * 136 + 8]);
                }
            }
#pragma unroll
            for (int na = 0; na < 4; na++) {
                int c = wc * 32 + na * 8 + g;
                if (BKC) {
                    const float* p = Bs_ + c * 20 + kb;
                    bq[na][0] = tfu(p[0]);       bq[na][1] = tfu(p[4]);
                } else {
                    const float* p = Bs_ + kb * 136 + c;
                    bq[na][0] = tfu(p[0]);       bq[na][1] = tfu(p[4 * 136]);
                }
            }
#pragma unroll
            for (int ma = 0; ma < 4; ma++)
#pragma unroll
                for (int na = 0; na < 4; na++)
                    mma8(acc[ma][na], a[ma], bq[na]);
        }
        if (kt + 3 < KT) issue((kt + 3) & 3, (kt + 3) << 4);
        cp_commit();
        cp_wait2();
        __syncthreads();
    }
#pragma unroll
    for (int ma = 0; ma < 4; ma++)
#pragma unroll
        for (int hf = 0; hf < 2; hf++) {
            int gm = m0 + wr * 64 + ma * 16 + hf * 8 + g;
#pragma unroll
            for (int na = 0; na < 4; na++) {
                int gn = n0 + wc * 32 + na * 8 + 2 * tg;
                float2 o;
                o.x = acc[ma][na][hf * 2];
                o.y = acc[ma][na][hf * 2 + 1];
                *(float2*)&C[(size_t)gm * sCm + gn] = o;
            }
        }
}

// ---------------- RoPE kernels (in-place) ----------------
__global__ void rope_qr_kernel(float* __restrict__ qr,
                               const float* __restrict__ cs, const float* __restrict__ sn)
{
    int idx = blockIdx.x * blockDim.x + threadIdx.x;
    if (idx >= BB * TT * NH_ * 32) return;
    int i  = idx & 31;
    int h  = (idx >> 5) & 15;
    int bt = idx >> 9;
    int t  = bt & (TT - 1);
    float c = cs[t * 32 + i], s = sn[t * 32 + i];
    size_t base = (size_t)bt * (NH_ * DHR_) + h * DHR_ + 2 * i;
    float re = qr[base], im = qr[base + 1];
    qr[base]     = re * c - im * s;
    qr[base + 1] = re * s + im * c;
}

__global__ void rope_kr_kernel(float* __restrict__ kr,
                               const float* __restrict__ cs, const float* __restrict__ sn)
{
    int idx = blockIdx.x * blockDim.x + threadIdx.x;
    if (idx >= BB * TT * 32) return;
    int i  = idx & 31;
    int bt = idx >> 5;
    int t  = bt & (TT - 1);
    float c = cs[t * 32 + i], s = sn[t * 32 + i];
    size_t base = (size_t)bt * DHR_ + 2 * i;
    float re = kr[base], im = kr[base + 1];
    kr[base]     = re * c - im * s;
    kr[base + 1] = re * s + im * c;
}

// ---------------- tf32 tensor-core flash attention v3 (unchanged from R14) ----------------
#define QCP 68
#define PP  68
#define KCP 72
#define VPP 520
#define QBUF (64 * QCP)
#define KBUF (64 * KCP)
#define FTC_FLOATS (2*QBUF + 2*KBUF + 64*VPP + 64*PP + 64*8 + 4*64)

__global__ __launch_bounds__(256, 1) void flash_tc(
    const float* __restrict__ qlat, const float* __restrict__ qr,
    const float* __restrict__ ckv,  const float* __restrict__ kr,
    float* __restrict__ ctx)
{
    extern __shared__ float smx[];
    float* Qb  = smx;
    float* Kb  = Qb + 2 * QBUF;
    float* Vs  = Kb + 2 * KBUF;
    float* Ps  = Vs + 64 * VPP;
    float* Red = Ps + 64 * PP;
    float* msm = Red + 64 * 8;
    float* lsm = msm + 64;
    float* fsm = lsm + 64;
    float* mns = fsm + 64;

    int qt = blockIdx.x, h = blockIdx.y, b = blockIdx.z;
    int t0 = qt * 64;
    int tid = threadIdx.x, lane = tid & 31, w = tid >> 5;
    int g = lane >> 2, tg = lane & 3;
    int wr = w & 1, wc = w >> 1;
    const float scale = rsqrtf((float)(HS_ + DHR_));

    const float* qlatp = qlat + ((size_t)(b * NH_ + h) * TT + t0) * NLKV_;
    const float* qrp   = qr   + ((size_t)b * TT + t0) * (NH_ * DHR_) + h * DHR_;
    const float* ckvb  = ckv  + (size_t)b * TT * NLKV_;
    const float* krb   = kr   + (size_t)b * TT * DHR_;

    float kst[16], vst[16];

    auto fetchK = [&](int s0v, int dc) {
        int j = tid >> 2;
        int db = (tid & 3) * 16;
        const float* src = (dc < 8)
            ? (ckvb + (size_t)(s0v + j) * NLKV_ + dc * 64 + db)
            : (krb  + (size_t)(s0v + j) * DHR_ + db);
#pragma unroll
        for (int u = 0; u < 16; u += 4) {
            float4 v = *(const float4*)(src + u);
            kst[u] = v.x; kst[u+1] = v.y; kst[u+2] = v.z; kst[u+3] = v.w;
        }
    };
    auto storeK = [&](float* kb) {
        int j = tid >> 2;
        int db = (tid & 3) * 16;
#pragma unroll
        for (int u = 0; u < 16; u++) kb[(db + u) * KCP + j] = tf(kst[u]);
    };
    auto fetchV = [&](int s0v, int sl) {
#pragma unroll
        for (int u = 0; u < 4; u++) {
            int i4 = tid + (sl * 4 + u) * 256;
            int r = i4 >> 7, c4 = (i4 & 127) * 4;
            float4 v = *(const float4*)(ckvb + (size_t)(s0v + r) * NLKV_ + c4);
            vst[u*4] = v.x; vst[u*4+1] = v.y; vst[u*4+2] = v.z; vst[u*4+3] = v.w;
        }
    };
    auto storeV = [&](int sl) {
#pragma unroll
        for (int u = 0; u < 4; u++) {
            int i4 = tid + (sl * 4 + u) * 256;
            int r = i4 >> 7, c4 = (i4 & 127) * 4;
            float* d = Vs + r * VPP + c4;
            d[0] = tf(vst[u*4]);   d[1] = tf(vst[u*4+1]);
            d[2] = tf(vst[u*4+2]); d[3] = tf(vst[u*4+3]);
        }
    };
    auto loadQdir = [&](int dc, float* qb) {
#pragma unroll
        for (int u = 0; u < 4; u++) {
            int i4 = tid + u * 256;
            int r = i4 >> 4, c4 = (i4 & 15) * 4;
            float4 v;
            if (dc < 8) v = *(const float4*)(qlatp + (size_t)r * NLKV_ + dc * 64 + c4);
            else        v = *(const float4*)(qrp  + (size_t)r * (NH_ * DHR_) + c4);
            float4 o;
            o.x = tf(v.x * scale); o.y = tf(v.y * scale);
            o.z = tf(v.z * scale); o.w = tf(v.w * scale);
            *(float4*)(qb + r * QCP + c4) = o;
        }
    };

    if (tid < 64) { msm[tid] = -1e30f; lsm[tid] = 0.f; }

    float O[2][16][4];
#pragma unroll
    for (int ma = 0; ma < 2; ma++)
#pragma unroll
        for (int na = 0; na < 16; na++)
#pragma unroll
            for (int c = 0; c < 4; c++) O[ma][na][c] = 0.f;

    loadQdir(0, Qb);
    fetchK(0, 0);
    storeK(Kb);
    __syncthreads();

    for (int kt = 0; kt <= qt; kt++) {
        int s0 = kt * 64;
        float S[2][2][4];
#pragma unroll
        for (int ma = 0; ma < 2; ma++)
#pragma unroll
            for (int na = 0; na < 2; na++)
#pragma unroll
                for (int c = 0; c < 4; c++) S[ma][na][c] = 0.f;

        for (int dc = 0; dc < 9; dc++) {
            const float* qc = Qb + (dc & 1) * QBUF;
            const float* kc = Kb + (dc & 1) * KBUF;
            if (dc < 8) {
                fetchK(s0, dc + 1);
                fetchV(s0, dc);
                loadQdir(dc + 1, Qb + ((dc + 1) & 1) * QBUF);
            }
#pragma unroll
            for (int kk = 0; kk < 8; kk++) {
                unsigned a[2][4], bq[2][2];
#pragma unroll
                for (int ma = 0; ma < 2; ma++) {
                    const float* p = qc + (wr * 32 + ma * 16 + g) * QCP + kk * 8 + tg;
                    a[ma][0] = __float_as_uint(p[0]);
                    a[ma][1] = __float_as_uint(p[8 * QCP]);
                    a[ma][2] = __float_as_uint(p[4]);
                    a[ma][3] = __float_as_uint(p[8 * QCP + 4]);
                }
#pragma unroll
                for (int na = 0; na < 2; na++) {
                    const float* p = kc + (kk * 8 + tg) * KCP + wc * 16 + na * 8 + g;
                    bq[na][0] = __float_as_uint(p[0]);
                    bq[na][1] = __float_as_uint(p[4 * KCP]);
                }
#pragma unroll
                for (int ma = 0; ma < 2; ma++)
#pragma unroll
                    for (int na = 0; na < 2; na++)
                        mma8(S[ma][na], a[ma], bq[na]);
            }
            if (dc < 8) {
                storeK(Kb + ((dc + 1) & 1) * KBUF);
                storeV(dc);
            }
            __syncthreads();
        }

        if (kt == qt) {
#pragma unroll
            for (int ma = 0; ma < 2; ma++)
#pragma unroll
                for (int na = 0; na < 2; na++)
#pragma unroll
                    for (int ci = 0; ci < 4; ci++) {
                        int row = wr * 32 + ma * 16 + (ci >> 1) * 8 + g;
                        int col = wc * 16 + na * 8 + 2 * tg + (ci & 1);
                        if (col > row) S[ma][na][ci] = -1e30f;
                    }
        }

#pragma unroll
        for (int ma = 0; ma < 2; ma++)
#pragma unroll
            for (int hf = 0; hf < 2; hf++) {
                float v = fmaxf(fmaxf(S[ma][0][hf * 2], S[ma][0][hf * 2 + 1]),
                                fmaxf(S[ma][1][hf * 2], S[ma][1][hf * 2 + 1]));
                v = fmaxf(v, __shfl_xor_sync(0xffffffffu, v, 1));
                v = fmaxf(v, __shfl_xor_sync(0xffffffffu, v, 2));
                if (tg == 0)
                    Red[(wr * 32 + ma * 16 + hf * 8 + g) * 8 + wc] = v;
            }
        __syncthreads();
        if (tid < 64) {
            float mx = fmaxf(fmaxf(Red[tid * 8 + 0], Red[tid * 8 + 1]),
                             fmaxf(Red[tid * 8 + 2], Red[tid * 8 + 3]));
            float mo = msm[tid];
            float mn = fmaxf(mo, mx);
            msm[tid] = mn; mns[tid] = mn;
            fsm[tid] = __expf(mo - mn);
        }
        __syncthreads();

#pragma unroll
        for (int ma = 0; ma < 2; ma++)
#pragma unroll
            for (int hf = 0; hf < 2; hf++) {
                int row = wr * 32 + ma * 16 + hf * 8 + g;
                float mn = mns[row];
                float s = 0.f;
#pragma unroll
                for (int na = 0; na < 2; na++) {
                    float p0 = __expf(S[ma][na][hf * 2 + 0] - mn);
                    float p1 = __expf(S[ma][na][hf * 2 + 1] - mn);
                    s += p0 + p1;
                    float2 pv; pv.x = tf(p0); pv.y = tf(p1);
                    *(float2*)(Ps + row * PP + wc * 16 + na * 8 + 2 * tg) = pv;
                }
                s += __shfl_xor_sync(0xffffffffu, s, 1);
                s += __shfl_xor_sync(0xffffffffu, s, 2);
                if (tg == 0) Red[row * 8 + 4 + wc] = s;
            }
#pragma unroll
        for (int ma = 0; ma < 2; ma++) {
            float f0 = fsm[wr * 32 + ma * 16 + g];
            float f1 = fsm[wr * 32 + ma * 16 + 8 + g];
#pragma unroll
            for (int na = 0; na < 16; na++) {
                O[ma][na][0] *= f0; O[ma][na][1] *= f0;
                O[ma][na][2] *= f1; O[ma][na][3] *= f1;
            }
        }
        __syncthreads();
        if (tid < 64)
            lsm[tid] = lsm[tid] * fsm[tid] +
                       Red[tid * 8 + 4] + Red[tid * 8 + 5] +
                       Red[tid * 8 + 6] + Red[tid * 8 + 7];

        bool pre = (kt < qt);
        if (pre) {
            loadQdir(0, Qb);
            fetchK(s0 + 64, 0);
        }

#pragma unroll
        for (int kk = 0; kk < 8; kk++) {
            unsigned a0[4], a1[4];
            int sc = kk * 8 + tg;
            {
                const float* p = Ps + (wr * 32 + g) * PP + sc;
                a0[0] = __float_as_uint(p[0]);
                a0[1] = __float_as_uint(p[8 * PP]);
                a0[2] = __float_as_uint(p[4]);
                a0[3] = __float_as_uint(p[8 * PP + 4]);
            }
            {
                const float* p = Ps + (wr * 32 + 16 + g) * PP + sc;
                a1[0] = __float_as_uint(p[0]);
                a1[1] = __float_as_uint(p[8 * PP]);
                a1[2] = __float_as_uint(p[4]);
                a1[3] = __float_as_uint(p[8 * PP + 4]);
            }
#pragma unroll
            for (int na = 0; na < 16; na++) {
                const float* p = Vs + (kk * 8 + tg) * VPP + wc * 128 + na * 8 + g;
                unsigned bq[2];
                bq[0] = __float_as_uint(p[0]);
                bq[1] = __float_as_uint(p[4 * VPP]);
                mma8(O[0][na], a0, bq);
                mma8(O[1][na], a1, bq);
            }
        }
        if (pre) storeK(Kb);
        __syncthreads();
    }

#pragma unroll
    for (int ma = 0; ma < 2; ma++)
#pragma unroll
        for (int hf = 0; hf < 2; hf++) {
            int row = wr * 32 + ma * 16 + hf * 8 + g;
            float inv = 1.0f / lsm[row];
            float* orow = ctx + ((size_t)(b * NH_ + h) * TT + t0 + row) * NLKV_;
#pragma unroll
            for (int na = 0; na < 16; na++) {
                float2 o;
                o.x = O[ma][na][hf * 2]     * inv;
                o.y = O[ma][na][hf * 2 + 1] * inv;
                *(float2*)(orow + wc * 128 + na * 8 + 2 * tg) = o;
            }
        }
}

// ---------------- launch ----------------
extern "C" void kernel_launch(void* const* d_in, const int* in_sizes, int n_in,
                              void* d_out, int out_size)
{
    (void)in_sizes; (void)n_in; (void)out_size;
    const float* x    = (const float*)d_in[0];
    const float* cs   = (const float*)d_in[1];
    const float* sn   = (const float*)d_in[2];
    const float* W_dq = (const float*)d_in[3];
    const float* W_uq = (const float*)d_in[4];
    const float* W_dkv= (const float*)d_in[5];
    const float* W_uk = (const float*)d_in[6];
    const float* W_uv = (const float*)d_in[7];
    const float* W_qr = (const float*)d_in[8];
    const float* W_kr = (const float*)d_in[9];
    const float* W_o  = (const float*)d_in[10];
    float* y = (float*)d_out;

    float *cq, *ckv, *keff, *vtmp, *qlat, *qr, *kr, *ctx;
    cudaGetSymbolAddress((void**)&cq,   d_cq);
    cudaGetSymbolAddress((void**)&ckv,  d_ckv);
    cudaGetSymbolAddress((void**)&keff, d_keff);
    cudaGetSymbolAddress((void**)&vtmp, d_vtmp);
    cudaGetSymbolAddress((void**)&qlat, d_qlat);
    cudaGetSymbolAddress((void**)&qr,   d_qr);
    cudaGetSymbolAddress((void**)&kr,   d_kr);
    cudaGetSymbolAddress((void**)&ctx,  d_ctx);

    const int MT = BB * TT;   // 4096

    // dynamic smem sizes: 4 stages x (ASZ+BSZ) floats
    const int smem11 = 4 * (128*20 + 128*20) * 4;   // 81920 B
    const int smem10 = 4 * (128*20 + 16*136) * 4;   // 75776 B
    const int smem01 = 4 * (16*136 + 128*20) * 4;   // 75776 B
    cudaFuncSetAttribute((const void*)tgemm_t<1,1>,
                         cudaFuncAttributeMaxDynamicSharedMemorySize, smem11);
    cudaFuncSetAttribute((const void*)tgemm_t<1,0>,
                         cudaFuncAttributeMaxDynamicSharedMemorySize, smem10);
    cudaFuncSetAttribute((const void*)tgemm_t<0,1>,
                         cudaFuncAttributeMaxDynamicSharedMemorySize, smem01);

    // 1) c_q = x @ W_dq^T   (A k-contig, B k-contig)
    tgemm_t<1,1><<<dim3(NLQ_/128, MT/128, 1), 256, smem11>>>(x, W_dq, cq,
        MT, NLQ_, CC,  CC,1, 0,0,  CC,1, 0,0,  NLQ_, 0,0, 1);

    // 2) c_kv = x @ W_dkv^T
    tgemm_t<1,1><<<dim3(NLKV_/128, MT/128, 1), 256, smem11>>>(x, W_dkv, ckv,
        MT, NLKV_, CC,  CC,1, 0,0,  CC,1, 0,0,  NLKV_, 0,0, 1);

    // 3) k_eff  (A k-contig, B n-contig)
    tgemm_t<1,0><<<dim3(NLKV_/128, NLQ_/128, NH_), 256, smem10>>>(W_uq, W_uk, keff,
        NLQ_, NLKV_, HS_,
        CC,1, 0,(long long)HS_,
        1,(long long)NLKV_, 0,(long long)HS_*NLKV_,
        NLKV_, 0,(long long)NLQ_*NLKV_, NH_);

    // 4) v_tmp = W_uv^T @ W_o^T   (A m-contig, B k-contig)
    tgemm_t<0,1><<<dim3(CC/128, NLKV_/128, 1), 256, smem01>>>(W_uv, W_o, vtmp,
        NLKV_, CC, CC,
        1,(long long)NLKV_, 0,0,
        CC,1, 0,0,
        CC, 0,0, 1);

    // 5) qr_lin = c_q @ W_qr^T
    tgemm_t<1,1><<<dim3((NH_*DHR_)/128, MT/128, 1), 256, smem11>>>(cq, W_qr, qr,
        MT, NH_*DHR_, NLQ_,  NLQ_,1, 0,0,  NLQ_,1, 0,0,  NH_*DHR_, 0,0, 1);

    // 6) kr_lin = x @ W_kr^T   (fp32, small: N=64)
    sgemm_g<<<dim3(1, MT/64, 1), 256>>>(x, W_kr, kr,
        MT, DHR_, CC,  CC,1, 0,0,  CC,1, 0,0,  DHR_, 0,0, 1);

    // 7) RoPE (in place)
    rope_qr_kernel<<<(BB*TT*NH_*32 + 255)/256, 256>>>(qr, cs, sn);
    rope_kr_kernel<<<(BB*TT*32 + 255)/256, 256>>>(kr, cs, sn);

    // 8) q_lat = c_q @ k_eff   (A k-contig, B n-contig)
    tgemm_t<1,0><<<dim3(NLKV_/128, TT/128, BB*NH_), 256, smem10>>>(cq, keff, qlat,
        TT, NLKV_, NLQ_,
        NLQ_,1, (long long)TT*NLQ_, 0,
        1,(long long)NLKV_, 0,(long long)NLQ_*NLKV_,
        NLKV_, (long long)NH_*TT*NLKV_, (long long)TT*NLKV_, NH_);

    // 9) flash attention core v3 -> ctx
    static const size_t smem_bytes = (size_t)FTC_FLOATS * sizeof(float);
    cudaFuncSetAttribute(flash_tc, cudaFuncAttributeMaxDynamicSharedMemorySize,
                         (int)smem_bytes);
    flash_tc<<<dim3(TT/64, NH_, BB), 256, smem_bytes>>>(qlat, qr, ckv, kr, ctx);

    // 10) y = ctx @ v_eff   (A k-contig, B n-contig)
    tgemm_t<1,0><<<dim3(HS_/128, TT/128, BB*NH_), 256, smem10>>>(ctx, vtmp, y,
        TT, HS_, NLKV_,
        NLKV_,1, (long long)NH_*TT*NLKV_, (long long)TT*NLKV_,
        1,(long long)CC, 0,(long long)HS_,
        CC, (long long)TT*CC, (long long)HS_, NH_);
}

// round 16
// speedup vs baseline: 2.7621x; 1.0062x over previous
#include <cuda_runtime.h>
#include <math.h>

// Problem constants
#define BB   2
#define TT   2048
#define CC   2048
#define NH_  16
#define HS_  128
#define NLQ_ 512
#define NLKV_ 512
#define DHR_ 64

// ---------------- scratch buffers ----------------
__device__ __align__(16) float d_cq   [(size_t)BB*TT*NLQ_];
__device__ __align__(16) float d_ckv  [(size_t)BB*TT*NLKV_];
__device__ __align__(16) float d_qfull[(size_t)BB*TT*CC];
__device__ __align__(16) float d_vtmp [(size_t)NLKV_*CC];
__device__ __align__(16) float d_qlat [(size_t)BB*NH_*TT*NLKV_];
__device__ __align__(16) float d_qr   [(size_t)BB*TT*NH_*DHR_];
__device__ __align__(16) float d_kr   [(size_t)BB*TT*DHR_];
__device__ __align__(16) float d_ctx  [(size_t)BB*NH_*TT*NLKV_];

// ---------------- tf32 / async helpers ----------------
__device__ __forceinline__ float tf(float x) {
    unsigned r; asm("cvt.rna.tf32.f32 %0, %1;" : "=r"(r) : "f"(x));
    return __uint_as_float(r);
}
__device__ __forceinline__ unsigned tfu(float x) {
    unsigned r; asm("cvt.rna.tf32.f32 %0, %1;" : "=r"(r) : "f"(x));
    return r;
}
__device__ __forceinline__ void mma8(float d[4], const unsigned a[4], const unsigned b[2]) {
    asm volatile(
        "mma.sync.aligned.m16n8k8.row.col.f32.tf32.tf32.f32 "
        "{%0,%1,%2,%3}, {%4,%5,%6,%7}, {%8,%9}, {%0,%1,%2,%3};\n"
        : "+f"(d[0]), "+f"(d[1]), "+f"(d[2]), "+f"(d[3])
        : "r"(a[0]), "r"(a[1]), "r"(a[2]), "r"(a[3]), "r"(b[0]), "r"(b[1]));
}
__device__ __forceinline__ void cp16(unsigned d, const float* s) {
    asm volatile("cp.async.ca.shared.global [%0], [%1], 16;" :: "r"(d), "l"(s));
}
__device__ __forceinline__ void cp_commit() { asm volatile("cp.async.commit_group;"); }
__device__ __forceinline__ void cp_wait2()  { asm volatile("cp.async.wait_group 2;"); }

// ---------------- generic strided fp32 SGEMM (small leftovers only) ----------------
__global__ __launch_bounds__(256) void sgemm_g(
    const float* __restrict__ A, const float* __restrict__ B, float* __restrict__ C,
    int M, int N, int K,
    long long sAm, long long sAk, long long sAb, long long sAh,
    long long sBn, long long sBk, long long sBb, long long sBh,
    long long sCm, long long sCb, long long sCh, int H)
{
    __shared__ float As[16][68];
    __shared__ float Bs[16][68];

    int z = blockIdx.z;
    int bb = z / H, hh = z - bb * H;
    A += (size_t)bb * sAb + (size_t)hh * sAh;
    B += (size_t)bb * sBb + (size_t)hh * sBh;
    C += (size_t)bb * sCb + (size_t)hh * sCh;

    int m0 = blockIdx.y * 64, n0 = blockIdx.x * 64;
    int tid = threadIdx.x;
    int tx = tid & 15, ty = tid >> 4;

    float acc[4][4];
#pragma unroll
    for (int i = 0; i < 4; i++)
#pragma unroll
        for (int j = 0; j < 4; j++) acc[i][j] = 0.f;

    for (int k0 = 0; k0 < K; k0 += 16) {
#pragma unroll
        for (int u = 0; u < 4; u++) {
            int idx = tid * 4 + u;
            int m = idx >> 4, kk = idx & 15;
            int gm = m0 + m, gk = k0 + kk;
            As[kk][m] = (gm < M && gk < K) ? A[(size_t)gm * sAm + (size_t)gk * sAk] : 0.f;
            int gn = n0 + m;
            Bs[kk][m] = (gn < N && gk < K) ? B[(size_t)gn * sBn + (size_t)gk * sBk] : 0.f;
        }
        __syncthreads();
#pragma unroll
        for (int kk = 0; kk < 16; kk++) {
            float4 av = *(const float4*)&As[kk][ty << 2];
            float4 bv = *(const float4*)&Bs[kk][tx << 2];
            float a[4] = {av.x, av.y, av.z, av.w};
            float b[4] = {bv.x, bv.y, bv.z, bv.w};
#pragma unroll
            for (int i = 0; i < 4; i++)
#pragma unroll
                for (int j = 0; j < 4; j++)
                    acc[i][j] = fmaf(a[i], b[j], acc[i][j]);
        }
        __syncthreads();
    }
#pragma unroll
    for (int i = 0; i < 4; i++) {
        int gm = m0 + (ty << 2) + i;
        if (gm >= M) continue;
#pragma unroll
        for (int j = 0; j < 4; j++) {
            int gn = n0 + (tx << 2) + j;
            if (gn < N) C[(size_t)gm * sCm + gn] = acc[i][j];
        }
    }
}

// ---------------- tf32 tensor GEMM, 4-stage cp.async pipeline ----------------
// AKC=1: A k-contig (sAk==1); AKC=0 assumes sAm==1. BKC likewise for B.
// 128x128 block, 256 threads, warp grid 2(m) x 4(n), warp tile 64x32.
// REQUIRES M%128==0, N%128==0, K%16==0, K>=48.
template<int AKC, int BKC>
__global__ __launch_bounds__(256, 2) void tgemm_t(
    const float* __restrict__ A, const float* __restrict__ B, float* __restrict__ C,
    int M, int N, int K,
    long long sAm, long long sAk, long long sAb, long long sAh,
    long long sBn, long long sBk, long long sBb, long long sBh,
    long long sCm, long long sCb, long long sCh, int H)
{
    extern __shared__ float smp[];
    constexpr int ASZ = AKC ? 128 * 20 : 16 * 136;
    constexpr int BSZ = BKC ? 128 * 20 : 16 * 136;
    constexpr int STG = ASZ + BSZ;

    int z = blockIdx.z;
    int bb = z / H, hh = z - bb * H;
    A += (size_t)bb * sAb + (size_t)hh * sAh;
    B += (size_t)bb * sBb + (size_t)hh * sBh;
    C += (size_t)bb * sCb + (size_t)hh * sCh;

    int m0 = blockIdx.y * 128, n0 = blockIdx.x * 128;
    int tid = threadIdx.x, lane = tid & 31, w = tid >> 5;
    int g = lane >> 2, tg = lane & 3;
    int wr = w & 1, wc = w >> 1;

    unsigned sbase = (unsigned)__cvta_generic_to_shared(smp);

    float acc[4][4][4];
#pragma unroll
    for (int i = 0; i < 4; i++)
#pragma unroll
        for (int j = 0; j < 4; j++)
#pragma unroll
            for (int c = 0; c < 4; c++) acc[i][j][c] = 0.f;

    auto issue = [&](int s, int kof) {
        if (AKC) {
            int m = tid >> 1, h2 = (tid & 1) * 8;
            const float* gp = A + (size_t)(m0 + m) * sAm + kof + h2;
            unsigned d = sbase + (unsigned)((s * STG + m * 20 + h2) * 4);
            cp16(d, gp); cp16(d + 16, gp + 4);
        } else {
            int kk = tid & 15, ms = (tid >> 4) * 8;
            const float* gp = A + (size_t)(m0 + ms) + (size_t)(kof + kk) * sAk;
            unsigned d = sbase + (unsigned)((s * STG + kk * 136 + ms) * 4);
            cp16(d, gp); cp16(d + 16, gp + 4);
        }
        if (BKC) {
            int n = tid >> 1, h2 = (tid & 1) * 8;
            const float* gp = B + (size_t)(n0 + n) * sBn + kof + h2;
            unsigned d = sbase + (unsigned)((s * STG + ASZ + n * 20 + h2) * 4);
            cp16(d, gp); cp16(d + 16, gp + 4);
        } else {
            int kk = tid & 15, ns = (tid >> 4) * 8;
            const float* gp = B + (size_t)(n0 + ns) + (size_t)(kof + kk) * sBk;
            unsigned d = sbase + (unsigned)((s * STG + ASZ + kk * 136 + ns) * 4);
            cp16(d, gp); cp16(d + 16, gp + 4);
        }
    };

    const int KT = K >> 4;
    issue(0, 0);  cp_commit();
    issue(1, 16); cp_commit();
    issue(2, 32); cp_commit();
    cp_wait2();
    __syncthreads();

    for (int kt = 0; kt < KT; kt++) {
        int s = kt & 3;
        const float* As_ = smp + s * STG;
        const float* Bs_ = smp + s * STG + ASZ;
#pragma unroll
        for (int kk2 = 0; kk2 < 2; kk2++) {
            int kb = kk2 * 8 + tg;
            unsigned a[4][4], bq[4][2];
#pragma unroll
            for (int ma = 0; ma < 4; ma++) {
                int r = wr * 64 + ma * 16 + g;
                if (AKC) {
                    const float* p = As_ + r * 20 + kb;
                    a[ma][0] = tfu(p[0]);        a[ma][1] = tfu(p[8 * 20]);
                    a[ma][2] = tfu(p[4]);        a[ma][3] = tfu(p[8 * 20 + 4]);
                } else {
                    const float* p = As_ + kb * 136 + r;
                    a[ma][0] = tfu(p[0]);        a[ma][1] = tfu(p[8]);
                    a[ma][2] = tfu(p[4 * 136]);  a[ma][3] = tfu(p[4 * 136 + 8]);
                }
            }
#pragma unroll
            for (int na = 0; na < 4; na++) {
                int c = wc * 32 + na * 8 + g;
                if (BKC) {
                    const float* p = Bs_ + c * 20 + kb;
                    bq[na][0] = tfu(p[0]);       bq[na][1] = tfu(p[4]);
                } else {
                    const float* p = Bs_ + kb * 136 + c;
                    bq[na][0] = tfu(p[0]);       bq[na][1] = tfu(p[4 * 136]);
                }
            }
#pragma unroll
            for (int ma = 0; ma < 4; ma++)
#pragma unroll
                for (int na = 0; na < 4; na++)
                    mma8(acc[ma][na], a[ma], bq[na]);
        }
        if (kt + 3 < KT) issue((kt + 3) & 3, (kt + 3) << 4);
        cp_commit();
        cp_wait2();
        __syncthreads();
    }
#pragma unroll
    for (int ma = 0; ma < 4; ma++)
#pragma unroll
        for (int hf = 0; hf < 2; hf++) {
            int gm = m0 + wr * 64 + ma * 16 + hf * 8 + g;
#pragma unroll
            for (int na = 0; na < 4; na++) {
                int gn = n0 + wc * 32 + na * 8 + 2 * tg;
                float2 o;
                o.x = acc[ma][na][hf * 2];
                o.y = acc[ma][na][hf * 2 + 1];
                *(float2*)&C[(size_t)gm * sCm + gn] = o;
            }
        }
}

// ---------------- RoPE kernels (in-place) ----------------
__global__ void rope_qr_kernel(float* __restrict__ qr,
                               const float* __restrict__ cs, const float* __restrict__ sn)
{
    int idx = blockIdx.x * blockDim.x + threadIdx.x;
    if (idx >= BB * TT * NH_ * 32) return;
    int i  = idx & 31;
    int h  = (idx >> 5) & 15;
    int bt = idx >> 9;
    int t  = bt & (TT - 1);
    float c = cs[t * 32 + i], s = sn[t * 32 + i];
    size_t base = (size_t)bt * (NH_ * DHR_) + h * DHR_ + 2 * i;
    float re = qr[base], im = qr[base + 1];
    qr[base]     = re * c - im * s;
    qr[base + 1] = re * s + im * c;
}

__global__ void rope_kr_kernel(float* __restrict__ kr,
                               const float* __restrict__ cs, const float* __restrict__ sn)
{
    int idx = blockIdx.x * blockDim.x + threadIdx.x;
    if (idx >= BB * TT * 32) return;
    int i  = idx & 31;
    int bt = idx >> 5;
    int t  = bt & (TT - 1);
    float c = cs[t * 32 + i], s = sn[t * 32 + i];
    size_t base = (size_t)bt * DHR_ + 2 * i;
    float re = kr[base], im = kr[base + 1];
    kr[base]     = re * c - im * s;
    kr[base + 1] = re * s + im * c;
}

// ---------------- tf32 flash attention v4: 64q x 128-key tiles ----------------
// Q/K double-buffered per d-chunk (register-staged, fetch/store split around mma),
// V streamed in 8-row double-buffered chunks during PV. Warp grid 2(m) x 4(n).
#define QCP2 68     // Q chunk pitch (4 mod 32)
#define KCP2 136    // K chunk pitch (8 mod 32), 128 keys
#define VPP2 520    // V chunk pitch (8 mod 32)
#define PP2  132    // P pitch (4 mod 32), 128 keys
#define QB2  (64 * QCP2)   // 4352
#define KB2  (64 * KCP2)   // 8704
#define VB2  (8 * VPP2)    // 4160
#define FTC2_FLOATS (2*QB2 + 2*KB2 + 2*VB2 + 64*PP2 + 64*8 + 4*64)  // 43648 fl = 174592 B

__global__ __launch_bounds__(256, 1) void flash_tc2(
    const float* __restrict__ qlat, const float* __restrict__ qr,
    const float* __restrict__ ckv,  const float* __restrict__ kr,
    float* __restrict__ ctx)
{
    extern __shared__ float smx[];
    float* Qb  = smx;                 // 2 x [64][QCP2]
    float* Kb  = Qb + 2 * QB2;        // 2 x [64 d][KCP2]   ([d][key])
    float* Vb  = Kb + 2 * KB2;        // 2 x [8][VPP2]      ([key][d])
    float* Ps  = Vb + 2 * VB2;        // [64][PP2]
    float* Red = Ps + 64 * PP2;       // [64][8]
    float* msm = Red + 64 * 8;
    float* lsm = msm + 64;
    float* fsm = lsm + 64;
    float* mns = fsm + 64;

    int qt = blockIdx.x, h = blockIdx.y, b = blockIdx.z;
    int t0 = qt * 64;
    int NT = (qt + 2) >> 1;            // number of 128-key tiles
    int tid = threadIdx.x, lane = tid & 31, w = tid >> 5;
    int g = lane >> 2, tg = lane & 3;
    int wr = w & 1, wc = w >> 1;
    const float scale = rsqrtf((float)(HS_ + DHR_));

    const float* qlatp = qlat + ((size_t)(b * NH_ + h) * TT + t0) * NLKV_;
    const float* qrp   = qr   + ((size_t)b * TT + t0) * (NH_ * DHR_) + h * DHR_;
    const float* ckvb  = ckv  + (size_t)b * TT * NLKV_;
    const float* krb   = kr   + (size_t)b * TT * DHR_;

    float qst[16], kst[32], vst[16];

    auto fetchQ = [&](int dc) {
        int r = tid & 63, db = (tid >> 6) * 16;
        const float* src = (dc < 8)
            ? (qlatp + (size_t)r * NLKV_ + dc * 64 + db)
            : (qrp   + (size_t)r * (NH_ * DHR_) + db);
#pragma unroll
        for (int u = 0; u < 16; u += 4) {
            float4 v = *(const float4*)(src + u);
            qst[u] = v.x; qst[u+1] = v.y; qst[u+2] = v.z; qst[u+3] = v.w;
        }
    };
    auto storeQ = [&](float* qb) {
        int r = tid & 63, db = (tid >> 6) * 16;
        float* dst = qb + r * QCP2 + db;
#pragma unroll
        for (int u = 0; u < 16; u += 4) {
            float4 o;
            o.x = tf(qst[u]   * scale); o.y = tf(qst[u+1] * scale);
            o.z = tf(qst[u+2] * scale); o.w = tf(qst[u+3] * scale);
            *(float4*)(dst + u) = o;
        }
    };
    auto fetchK = [&](int s0v, int dc) {
        int j = tid & 127, hf = (tid >> 7) * 32;
        const float* src = (dc < 8)
            ? (ckvb + (size_t)(s0v + j) * NLKV_ + dc * 64 + hf)
            : (krb  + (size_t)(s0v + j) * DHR_ + hf);
#pragma unroll
        for (int u = 0; u < 32; u += 4) {
            float4 v = *(const float4*)(src + u);
            kst[u] = v.x; kst[u+1] = v.y; kst[u+2] = v.z; kst[u+3] = v.w;
        }
    };
    auto storeK = [&](float* kb) {
        int j = tid & 127, hf = (tid >> 7) * 32;
#pragma unroll
        for (int u = 0; u < 32; u++) kb[(hf + u) * KCP2 + j] = tf(kst[u]);
    };
    auto fetchV = [&](int s0v, int cc) {
#pragma unroll
        for (int u = 0; u < 4; u++) {
            int i4 = tid + u * 256;
            int r = i4 >> 7, c4 = (i4 & 127) * 4;
            float4 v = *(const float4*)(ckvb + (size_t)(s0v + cc * 8 + r) * NLKV_ + c4);
            vst[u*4] = v.x; vst[u*4+1] = v.y; vst[u*4+2] = v.z; vst[u*4+3] = v.w;
        }
    };
    auto storeV = [&](float* vb) {
#pragma unroll
        for (int u = 0; u < 4; u++) {
            int i4 = tid + u * 256;
            int r = i4 >> 7, c4 = (i4 & 127) * 4;
            float* d = vb + r * VPP2 + c4;
            d[0] = tf(vst[u*4]);   d[1] = tf(vst[u*4+1]);
            d[2] = tf(vst[u*4+2]); d[3] = tf(vst[u*4+3]);
        }
    };

    if (tid < 64) { msm[tid] = -1e30f; lsm[tid] = 0.f; }

    float O[2][16][4];
#pragma unroll
    for (int ma = 0; ma < 2; ma++)
#pragma unroll
        for (int na = 0; na < 16; na++)
#pragma unroll
            for (int c = 0; c < 4; c++) O[ma][na][c] = 0.f;

    // prime chunk 0 of tile 0
    fetchQ(0); fetchK(0, 0);
    storeQ(Qb); storeK(Kb);
    __syncthreads();

    for (int kt2 = 0; kt2 < NT; kt2++) {
        int s0 = kt2 * 128;
        float S[2][4][4];
#pragma unroll
        for (int ma = 0; ma < 2; ma++)
#pragma unroll
            for (int na = 0; na < 4; na++)
#pragma unroll
                for (int c = 0; c < 4; c++) S[ma][na][c] = 0.f;

        // ---- S phase: 9 d-chunks, Q+K double-buffered ----
        for (int dc = 0; dc < 9; dc++) {
            const float* qc = Qb + (dc & 1) * QB2;
            const float* kc = Kb + (dc & 1) * KB2;
            if (dc < 8) { fetchQ(dc + 1); fetchK(s0, dc + 1); }
#pragma unroll
            for (int kk = 0; kk < 8; kk++) {
                unsigned a[2][4], bq[4][2];
#pragma unroll
                for (int ma = 0; ma < 2; ma++) {
                    const float* p = qc + (wr * 32 + ma * 16 + g) * QCP2 + kk * 8 + tg;
                    a[ma][0] = __float_as_uint(p[0]);
                    a[ma][1] = __float_as_uint(p[8 * QCP2]);
                    a[ma][2] = __float_as_uint(p[4]);
                    a[ma][3] = __float_as_uint(p[8 * QCP2 + 4]);
                }
#pragma unroll
                for (int na = 0; na < 4; na++) {
                    const float* p = kc + (kk * 8 + tg) * KCP2 + wc * 32 + na * 8 + g;
                    bq[na][0] = __float_as_uint(p[0]);
                    bq[na][1] = __float_as_uint(p[4 * KCP2]);
                }
#pragma unroll
                for (int ma = 0; ma < 2; ma++)
#pragma unroll
                    for (int na = 0; na < 4; na++)
                        mma8(S[ma][na], a[ma], bq[na]);
            }
            if (dc < 8) {
                storeQ(Qb + ((dc + 1) & 1) * QB2);
                storeK(Kb + ((dc + 1) & 1) * KB2);
            }
            __syncthreads();
        }

        // causal mask (last tile only; global coords)
        if (kt2 == NT - 1) {
#pragma unroll
            for (int ma = 0; ma < 2; ma++)
#pragma unroll
                for (int na = 0; na < 4; na++)
#pragma unroll
                    for (int ci = 0; ci < 4; ci++) {
                        int row = t0 + wr * 32 + ma * 16 + (ci >> 1) * 8 + g;
                        int col = s0 + wc * 32 + na * 8 + 2 * tg + (ci & 1);
                        if (col > row) S[ma][na][ci] = -1e30f;
                    }
        }

        // ---- row max ----
#pragma unroll
        for (int ma = 0; ma < 2; ma++)
#pragma unroll
            for (int hf = 0; hf < 2; hf++) {
                float v = -1e30f;
#pragma unroll
                for (int na = 0; na < 4; na++)
                    v = fmaxf(v, fmaxf(S[ma][na][hf * 2], S[ma][na][hf * 2 + 1]));
                v = fmaxf(v, __shfl_xor_sync(0xffffffffu, v, 1));
                v = fmaxf(v, __shfl_xor_sync(0xffffffffu, v, 2));
                if (tg == 0)
                    Red[(wr * 32 + ma * 16 + hf * 8 + g) * 8 + wc] = v;
            }
        __syncthreads();
        if (tid < 64) {
            float mx = fmaxf(fmaxf(Red[tid * 8 + 0], Red[tid * 8 + 1]),
                             fmaxf(Red[tid * 8 + 2], Red[tid * 8 + 3]));
            float mo = msm[tid];
            float mn = fmaxf(mo, mx);
            msm[tid] = mn; mns[tid] = mn;
            fsm[tid] = __expf(mo - mn);
        }
        __syncthreads();

        // early V prefetch for PV chunk 0 (overlaps exp/rescale section)
        fetchV(s0, 0);

        // ---- exp, write P (tf32), partial sums, rescale O ----
#pragma unroll
        for (int ma = 0; ma < 2; ma++)
#pragma unroll
            for (int hf = 0; hf < 2; hf++) {
                int row = wr * 32 + ma * 16 + hf * 8 + g;
                float mn = mns[row];
                float s = 0.f;
#pragma unroll
                for (int na = 0; na < 4; na++) {
                    float p0 = __expf(S[ma][na][hf * 2 + 0] - mn);
                    float p1 = __expf(S[ma][na][hf * 2 + 1] - mn);
                    s += p0 + p1;
                    float2 pv; pv.x = tf(p0); pv.y = tf(p1);
                    *(float2*)(Ps + row * PP2 + wc * 32 + na * 8 + 2 * tg) = pv;
                }
                s += __shfl_xor_sync(0xffffffffu, s, 1);
                s += __shfl_xor_sync(0xffffffffu, s, 2);
                if (tg == 0) Red[row * 8 + 4 + wc] = s;
            }
#pragma unroll
        for (int ma = 0; ma < 2; ma++) {
            float f0 = fsm[wr * 32 + ma * 16 + g];
            float f1 = fsm[wr * 32 + ma * 16 + 8 + g];
#pragma unroll
            for (int na = 0; na < 16; na++) {
                O[ma][na][0] *= f0; O[ma][na][1] *= f0;
                O[ma][na][2] *= f1; O[ma][na][3] *= f1;
            }
        }
        __syncthreads();
        if (tid < 64)
            lsm[tid] = lsm[tid] * fsm[tid] +
                       Red[tid * 8 + 4] + Red[tid * 8 + 5] +
                       Red[tid * 8 + 6] + Red[tid * 8 + 7];

        // next-tile chunk-0 prefetch (covered by the whole PV phase)
        bool pre = (kt2 < NT - 1);
        if (pre) { fetchQ(0); fetchK(s0 + 128, 0); }

        storeV(Vb);
        __syncthreads();

        // ---- PV: 16 chunks of 8 keys, double-buffered ----
        for (int cc = 0; cc < 16; cc++) {
            const float* vb = Vb + (cc & 1) * VB2;
            if (cc < 15) fetchV(s0, cc + 1);
            unsigned a0[4], a1[4];
            int sc = cc * 8 + tg;
            {
                const float* p = Ps + (wr * 32 + g) * PP2 + sc;
                a0[0] = __float_as_uint(p[0]);
                a0[1] = __float_as_uint(p[8 * PP2]);
                a0[2] = __float_as_uint(p[4]);
                a0[3] = __float_as_uint(p[8 * PP2 + 4]);
            }
            {
                const float* p = Ps + (wr * 32 + 16 + g) * PP2 + sc;
                a1[0] = __float_as_uint(p[0]);
                a1[1] = __float_as_uint(p[8 * PP2]);
                a1[2] = __float_as_uint(p[4]);
                a1[3] = __float_as_uint(p[8 * PP2 + 4]);
            }
#pragma unroll
            for (int na = 0; na < 16; na++) {
                const float* p = vb + tg * VPP2 + wc * 128 + na * 8 + g;
                unsigned bq[2];
                bq[0] = __float_as_uint(p[0]);
                bq[1] = __float_as_uint(p[4 * VPP2]);
                mma8(O[0][na], a0, bq);
                mma8(O[1][na], a1, bq);
            }
            if (cc < 15) storeV(Vb + ((cc + 1) & 1) * VB2);
            __syncthreads();
        }

        if (pre) {
            storeQ(Qb);
            storeK(Kb);
            __syncthreads();
        }
    }

    // ---- epilogue: normalize and write ctx ----
#pragma unroll
    for (int ma = 0; ma < 2; ma++)
#pragma unroll
        for (int hf = 0; hf < 2; hf++) {
            int row = wr * 32 + ma * 16 + hf * 8 + g;
            float inv = 1.0f / lsm[row];
            float* orow = ctx + ((size_t)(b * NH_ + h) * TT + t0 + row) * NLKV_;
#pragma unroll
            for (int na = 0; na < 16; na++) {
                float2 o;
                o.x = O[ma][na][hf * 2]     * inv;
                o.y = O[ma][na][hf * 2 + 1] * inv;
                *(float2*)(orow + wc * 128 + na * 8 + 2 * tg) = o;
            }
        }
}

// ---------------- launch ----------------
extern "C" void kernel_launch(void* const* d_in, const int* in_sizes, int n_in,
                              void* d_out, int out_size)
{
    (void)in_sizes; (void)n_in; (void)out_size;
    const float* x    = (const float*)d_in[0];
    const float* cs   = (const float*)d_in[1];
    const float* sn   = (const float*)d_in[2];
    const float* W_dq = (const float*)d_in[3];
    const float* W_uq = (const float*)d_in[4];
    const float* W_dkv= (const float*)d_in[5];
    const float* W_uk = (const float*)d_in[6];
    const float* W_uv = (const float*)d_in[7];
    const float* W_qr = (const float*)d_in[8];
    const float* W_kr = (const float*)d_in[9];
    const float* W_o  = (const float*)d_in[10];
    float* y = (float*)d_out;

    float *cq, *ckv, *qfull, *vtmp, *qlat, *qr, *kr, *ctx;
    cudaGetSymbolAddress((void**)&cq,    d_cq);
    cudaGetSymbolAddress((void**)&ckv,   d_ckv);
    cudaGetSymbolAddress((void**)&qfull, d_qfull);
    cudaGetSymbolAddress((void**)&vtmp,  d_vtmp);
    cudaGetSymbolAddress((void**)&qlat,  d_qlat);
    cudaGetSymbolAddress((void**)&qr,    d_qr);
    cudaGetSymbolAddress((void**)&kr,    d_kr);
    cudaGetSymbolAddress((void**)&ctx,   d_ctx);

    const int MT = BB * TT;   // 4096

    const int smem11 = 4 * (128*20 + 128*20) * 4;
    const int smem10 = 4 * (128*20 + 16*136) * 4;
    const int smem01 = 4 * (16*136 + 128*20) * 4;
    cudaFuncSetAttribute((const void*)tgemm_t<1,1>,
                         cudaFuncAttributeMaxDynamicSharedMemorySize, smem11);
    cudaFuncSetAttribute((const void*)tgemm_t<1,0>,
                         cudaFuncAttributeMaxDynamicSharedMemorySize, smem10);
    cudaFuncSetAttribute((const void*)tgemm_t<0,1>,
                         cudaFuncAttributeMaxDynamicSharedMemorySize, smem01);

    // 1) c_q = x @ W_dq^T
    tgemm_t<1,1><<<dim3(NLQ_/128, MT/128, 1), 256, smem11>>>(x, W_dq, cq,
        MT, NLQ_, CC,  CC,1, 0,0,  CC,1, 0,0,  NLQ_, 0,0, 1);

    // 2) c_kv = x @ W_dkv^T
    tgemm_t<1,1><<<dim3(NLKV_/128, MT/128, 1), 256, smem11>>>(x, W_dkv, ckv,
        MT, NLKV_, CC,  CC,1, 0,0,  CC,1, 0,0,  NLKV_, 0,0, 1);

    // 3) q_full = c_q @ W_uq   (rank-128 factorization, stage 1)
    tgemm_t<1,0><<<dim3(CC/128, MT/128, 1), 256, smem10>>>(cq, W_uq, qfull,
        MT, CC, NLQ_,
        NLQ_,1, 0,0,
        1,(long long)CC, 0,0,
        CC, 0,0, 1);

    // 4) v_tmp = W_uv^T @ W_o^T
    tgemm_t<0,1><<<dim3(CC/128, NLKV_/128, 1), 256, smem01>>>(W_uv, W_o, vtmp,
        NLKV_, CC, CC,
        1,(long long)NLKV_, 0,0,
        CC,1, 0,0,
        CC, 0,0, 1);

    // 5) qr_lin = c_q @ W_qr^T
    tgemm_t<1,1><<<dim3((NH_*DHR_)/128, MT/128, 1), 256, smem11>>>(cq, W_qr, qr,
        MT, NH_*DHR_, NLQ_,  NLQ_,1, 0,0,  NLQ_,1, 0,0,  NH_*DHR_, 0,0, 1);

    // 6) kr_lin = x @ W_kr^T   (fp32, small)
    sgemm_g<<<dim3(1, MT/64, 1), 256>>>(x, W_kr, kr,
        MT, DHR_, CC,  CC,1, 0,0,  CC,1, 0,0,  DHR_, 0,0, 1);

    // 7) RoPE (in place)
    rope_qr_kernel<<<(BB*TT*NH_*32 + 255)/256, 256>>>(qr, cs, sn);
    rope_kr_kernel<<<(BB*TT*32 + 255)/256, 256>>>(kr, cs, sn);

    // 8) q_lat[b,h] = q_full_h @ W_uk_h   (rank-128 factorization, stage 2; K=128)
    tgemm_t<1,0><<<dim3(NLKV_/128, TT/128, BB*NH_), 256, smem10>>>(qfull, W_uk, qlat,
        TT, NLKV_, HS_,
        CC,1, (long long)TT*CC, (long long)HS_,
        1,(long long)NLKV_, 0,(long long)HS_*NLKV_,
        NLKV_, (long long)NH_*TT*NLKV_, (long long)TT*NLKV_, NH_);

    // 9) flash attention v4 (128-key tiles) -> ctx
    static const size_t smem_bytes = (size_t)FTC2_FLOATS * sizeof(float);
    cudaFuncSetAttribute(flash_tc2, cudaFuncAttributeMaxDynamicSharedMemorySize,
                         (int)smem_bytes);
    flash_tc2<<<dim3(TT/64, NH_, BB), 256, smem_bytes>>>(qlat, qr, ckv, kr, ctx);

    // 10) y = ctx @ v_eff
    tgemm_t<1,0><<<dim3(HS_/128, TT/128, BB*NH_), 256, smem10>>>(ctx, vtmp, y,
        TT, HS_, NLKV_,
        NLKV_,1, (long long)NH_*TT*NLKV_, (long long)TT*NLKV_,
        1,(long long)CC, 0,(long long)HS_,
        CC, (long long)TT*CC, (long long)HS_, NH_);
}